// round 11
// baseline (speedup 1.0000x reference)
#include <cuda_runtime.h>
#include <cstdint>

#define BB 64
#define NN 4096
#define SS 7

// ---------------- scratch (static device globals; no allocation) ----------------
__device__ unsigned g_k[BB * NN * 32];       // f16x2 words: 32 MB
__device__ unsigned g_v[BB * NN * 32];       // 32 MB
__device__ float g_q[BB * 448];              // q [b][s][64] (scaled by 1/8)
__device__ float g_slots[BB * SS * 64];
__device__ float g_numer[BB * 448];
__device__ float g_denom[BB * SS];
__device__ int   g_cnt[BB];                  // attn block-completion counters
__device__ unsigned g_Bt[128 * 32];          // B^T: [n][k] f16x2 words (Wk|Wv)
__device__ float g_wihT[64 * 192];           // GRU weights transposed [t][j]
__device__ float g_whhT[64 * 192];

// ---------------- helpers ----------------
__device__ __forceinline__ unsigned h2(float lo, float hi) {
    unsigned r;
    asm("cvt.rn.f16x2.f32 %0, %1, %2;" : "=r"(r) : "f"(hi), "f"(lo));
    return r;
}
__device__ __forceinline__ uint32_t smem_u32(const void* p) {
    uint32_t a;
    asm("{ .reg .u64 t; cvta.to.shared.u64 t, %1; cvt.u32.u64 %0, t; }" : "=r"(a) : "l"(p));
    return a;
}
__device__ __forceinline__ void mma_f16(float& c0, float& c1, float& c2, float& c3,
                                        unsigned a0, unsigned a1, unsigned a2, unsigned a3,
                                        unsigned b0, unsigned b1) {
    asm volatile(
        "mma.sync.aligned.m16n8k16.row.col.f32.f16.f16.f32 "
        "{%0,%1,%2,%3}, {%4,%5,%6,%7}, {%8,%9}, {%0,%1,%2,%3};"
        : "+f"(c0), "+f"(c1), "+f"(c2), "+f"(c3)
        : "r"(a0), "r"(a1), "r"(a2), "r"(a3), "r"(b0), "r"(b1));
}
#define LDSM4(r0, r1, r2, r3, a) \
    asm volatile("ldmatrix.sync.aligned.m8n8.x4.shared.b16 {%0,%1,%2,%3}, [%4];" \
        : "=r"(r0), "=r"(r1), "=r"(r2), "=r"(r3) : "r"(a))
#define LDSM4T(r0, r1, r2, r3, a) \
    asm volatile("ldmatrix.sync.aligned.m8n8.x4.trans.shared.b16 {%0,%1,%2,%3}, [%4];" \
        : "=r"(r0), "=r"(r1), "=r"(r2), "=r"(r3) : "r"(a))
#define CP16(dst, src) \
    asm volatile("cp.async.ca.shared.global [%0], [%1], 16;" :: "r"(dst), "l"(src))
#define CP_COMMIT() asm volatile("cp.async.commit_group;" ::: "memory")
#define CP_WAIT(n)  asm volatile("cp.async.wait_group %0;" :: "n"(n) : "memory")

// ---------------- common: LN(v over 64) with 2-warp block ----------------------
__device__ __forceinline__ float block_ln64(float v, int d, float* red) {
    float s1 = v, s2 = v * v;
#pragma unroll
    for (int o = 16; o; o >>= 1) {
        s1 += __shfl_xor_sync(0xffffffffu, s1, o);
        s2 += __shfl_xor_sync(0xffffffffu, s2, o);
    }
    const int wd = d >> 5;
    if ((d & 31) == 0) { red[wd] = s1; red[2 + wd] = s2; }
    __syncthreads();
    float S = red[0] + red[1], S2 = red[2] + red[3];
    float m = S * 0.015625f;
    float var = fmaxf(S2 * 0.015625f - m * m, 0.f);
    float inv = rsqrtf(var + 1e-5f);
    return (v - m) * inv;
}

// ---------------- kernel P: fused weight prep ----------------
__global__ void prep_kernel(const float* __restrict__ Wk, const float* __restrict__ Wv,
                            const float* __restrict__ wih, const float* __restrict__ whh) {
    int i = blockIdx.x * 256 + threadIdx.x;
    if (i < 4096) {
        int n = i >> 5, w = i & 31;
        const float* W = (n < 64) ? Wk : Wv;
        int nc = n & 63;
        g_Bt[i] = h2(W[(2 * w) * 64 + nc], W[(2 * w + 1) * 64 + nc]);
    } else if (i < 16384) {
        int m = i - 4096;
        int t = m / 192, j = m % 192;
        g_wihT[m] = wih[j * 64 + t];
    } else if (i < 28672) {
        int m = i - 16384;
        int t = m / 192, j = m % 192;
        g_whhT[m] = whh[j * 64 + t];
    }
}

// ---------------- kernel 0: init slots + q0 + zero accumulators -----------------
__global__ __launch_bounds__(64) void init_kernel(
    const float* __restrict__ s0,
    const float* __restrict__ lg, const float* __restrict__ lb,
    const float* __restrict__ Wq)
{
    const int bs = blockIdx.x;
    const int s = bs % SS;
    const int d = threadIdx.x;
    __shared__ float ssn[64];
    __shared__ float red[4];

    float v = s0[s * 64 + d];
    g_slots[bs * 64 + d] = v;

    float sn = block_ln64(v, d, red) * lg[d] + lb[d];
    ssn[d] = sn;
    __syncthreads();

    float q = 0.f;
#pragma unroll 8
    for (int j = 0; j < 64; j++) q += ssn[j] * Wq[j * 64 + d];
    g_q[bs * 64 + d] = q * 0.125f;
    g_numer[bs * 64 + d] = 0.f;
    if (d == 0) g_denom[bs] = 0.f;
    if (d == 0 && s == 0) g_cnt[bs / SS] = 0;
}

// ---------------- kernel 1: fused LN + f16 HMMA GEMM -> k|v ---------------------
#define PITCH 36
__global__ __launch_bounds__(256) void proj_kernel(
    const float* __restrict__ x,
    const float* __restrict__ lg, const float* __restrict__ lb)
{
    __shared__ __align__(16) unsigned sA[128 * PITCH];
    __shared__ __align__(16) unsigned sB[128 * PITCH];

    const int tid = threadIdx.x;
    const int w = tid >> 5, lane = tid & 31;
    const int row0 = blockIdx.x * 128;

    // stage B^T via cp.async (overlaps with the x LDGs below)
    const uint32_t sBb = smem_u32(sB);
    {
#pragma unroll
        for (int t = 0; t < 4; t++) {
            int q4 = t * 256 + tid;               // 16B unit index (1024 total)
            int n = q4 >> 3, m = q4 & 7;          // row n, word-group m
            CP16(sBb + (n * PITCH + m * 4) * 4, (const uint4*)g_Bt + q4);
        }
        CP_COMMIT();
    }

    const float4* x4 = (const float4*)(x + (size_t)row0 * 64);
    float4 f[8];
#pragma unroll
    for (int t = 0; t < 8; t++) f[t] = x4[t * 256 + tid];

    {
        const int j = tid & 15;
        const float4 gg = ((const float4*)lg)[j];
        const float4 bb = ((const float4*)lb)[j];
#pragma unroll
        for (int t = 0; t < 8; t++) {
            float4 v = f[t];
            float s1 = v.x + v.y + v.z + v.w;
            float s2 = v.x * v.x + v.y * v.y + v.z * v.z + v.w * v.w;
#pragma unroll
            for (int o = 1; o <= 8; o <<= 1) {
                s1 += __shfl_xor_sync(0xffffffffu, s1, o);
                s2 += __shfl_xor_sync(0xffffffffu, s2, o);
            }
            float m = s1 * 0.015625f;
            float var = fmaxf(s2 * 0.015625f - m * m, 0.f);
            float inv = rsqrtf(var + 1e-5f);
            float y0 = (v.x - m) * inv * gg.x + bb.x;
            float y1 = (v.y - m) * inv * gg.y + bb.y;
            float y2 = (v.z - m) * inv * gg.z + bb.z;
            float y3 = (v.w - m) * inv * gg.w + bb.w;
            int row = t * 16 + (tid >> 4);
            *(uint2*)&sA[row * PITCH + j * 2] = make_uint2(h2(y0, y1), h2(y2, y3));
        }
    }
    CP_WAIT(0);
    __syncthreads();

    const int r0 = w * 16;
    const int qr = lane >> 2, qc = lane & 3;
    const int ra = r0 + qr, rb = ra + 8;

    unsigned afr[4][4];
#pragma unroll
    for (int ks = 0; ks < 4; ks++) {
        afr[ks][0] = sA[ra * PITCH + qc + ks * 8];
        afr[ks][1] = sA[rb * PITCH + qc + ks * 8];
        afr[ks][2] = sA[ra * PITCH + qc + 4 + ks * 8];
        afr[ks][3] = sA[rb * PITCH + qc + 4 + ks * 8];
    }
    __syncthreads();

    // B-fragment ldmatrix base: lane group g in {0..3}; rows n8+(lane&7),
    // word offset = (g&1)*4 + (g>>1)*8 (+ pair*16 at use site).
    const uint32_t bB = sBb + ((((lane & 7)) * PITCH + ((lane >> 3) & 1) * 4 + (lane >> 4) * 8) << 2);

#pragma unroll
    for (int pass = 0; pass < 2; pass++) {
#pragma unroll
        for (int b8 = 0; b8 < 8; b8++) {
            float c0 = 0.f, c1 = 0.f, c2 = 0.f, c3 = 0.f;
            const uint32_t a0 = bB + (((pass * 8 + b8) * 8 * PITCH) << 2);
            unsigned q0, q1, q2, q3;
            LDSM4(q0, q1, q2, q3, a0);          // (ks0 b0, ks0 b1, ks1 b0, ks1 b1)
            mma_f16(c0, c1, c2, c3, afr[0][0], afr[0][1], afr[0][2], afr[0][3], q0, q1);
            mma_f16(c0, c1, c2, c3, afr[1][0], afr[1][1], afr[1][2], afr[1][3], q2, q3);
            LDSM4(q0, q1, q2, q3, a0 + 64);     // (ks2 b0, ks2 b1, ks3 b0, ks3 b1)
            mma_f16(c0, c1, c2, c3, afr[2][0], afr[2][1], afr[2][2], afr[2][3], q0, q1);
            mma_f16(c0, c1, c2, c3, afr[3][0], afr[3][1], afr[3][2], afr[3][3], q2, q3);
            sA[ra * PITCH + b8 * 4 + qc] = h2(c0, c1);
            sA[rb * PITCH + b8 * 4 + qc] = h2(c2, c3);
        }
        __syncthreads();
        unsigned* dst = pass ? g_v : g_k;
#pragma unroll
        for (int p = 0; p < 4; p++) {
            int row = p * 32 + (tid >> 3);
            uint4 val = *(uint4*)&sA[row * PITCH + (tid & 7) * 4];
            *(uint4*)&dst[(size_t)(row0 + row) * 32 + (tid & 7) * 4] = val;
        }
        __syncthreads();
    }
}

// ---------------- attn helpers ----------------
__device__ __forceinline__ void stage_cp(uint32_t base, const uint4* g, int l) {
    const uint32_t off = (((l >> 3)) * 36 + (l & 7) * 4) << 2;
#pragma unroll
    for (int i = 0; i < 8; i++)
        CP16(base + off + i * 576, g + i * 32 + l);
    CP_COMMIT();
}
__device__ __forceinline__ void ldsm_tiles(unsigned t[4][8], uint32_t base, int l, bool trans) {
#pragma unroll
    for (int g = 0; g < 4; g++)
#pragma unroll
        for (int cc = 0; cc < 2; cc++) {
            uint32_t a = base + (((8 * g + (l & 7)) * 36 + (4 * cc + (l >> 3)) * 4) << 2);
            if (trans) LDSM4T(t[g][4 * cc], t[g][4 * cc + 1], t[g][4 * cc + 2], t[g][4 * cc + 3], a);
            else       LDSM4 (t[g][4 * cc], t[g][4 * cc + 1], t[g][4 * cc + 2], t[g][4 * cc + 3], a);
        }
}
__device__ __forceinline__ float softmax_chunk(unsigned tiles[4][8], unsigned aq[4][2],
                                               float wreg[4][2], int s) {
    float dum0 = 0.f, dum1 = 0.f;
    float cl[4][2];
#pragma unroll
    for (int g = 0; g < 4; g++) {
        cl[g][0] = 0.f; cl[g][1] = 0.f;
#pragma unroll
        for (int ks = 0; ks < 4; ks++)
            mma_f16(cl[g][0], cl[g][1], dum0, dum1,
                    aq[ks][0], 0u, aq[ks][1], 0u, tiles[g][2 * ks], tiles[g][2 * ks + 1]);
    }
    float dl = 0.f;
#pragma unroll
    for (int g = 0; g < 4; g++) {
        float x0 = (s < 7) ? cl[g][0] : -1e30f;
        float x1 = (s < 7) ? cl[g][1] : -1e30f;
        float m0 = x0, m1 = x1;
#pragma unroll
        for (int o = 4; o <= 16; o <<= 1) {
            m0 = fmaxf(m0, __shfl_xor_sync(0xffffffffu, m0, o));
            m1 = fmaxf(m1, __shfl_xor_sync(0xffffffffu, m1, o));
        }
        float e0 = __expf(x0 - m0), e1 = __expf(x1 - m1);
        float t0 = e0, t1 = e1;
#pragma unroll
        for (int o = 4; o <= 16; o <<= 1) {
            t0 += __shfl_xor_sync(0xffffffffu, t0, o);
            t1 += __shfl_xor_sync(0xffffffffu, t1, o);
        }
        float w0 = (s < 7) ? e0 / t0 + 1e-8f : 0.f;
        float w1 = (s < 7) ? e1 / t1 + 1e-8f : 0.f;
        dl += w0 + w1;
        wreg[g][0] = w0; wreg[g][1] = w1;
    }
    return dl;
}
__device__ __forceinline__ void phase2_chunk(unsigned tiles[4][8], float wreg[4][2],
                                             float cu[8][2]) {
    float dum0 = 0.f, dum1 = 0.f;
    unsigned aw[2][2];
    aw[0][0] = h2(wreg[0][0], wreg[0][1]);
    aw[0][1] = h2(wreg[1][0], wreg[1][1]);
    aw[1][0] = h2(wreg[2][0], wreg[2][1]);
    aw[1][1] = h2(wreg[3][0], wreg[3][1]);
#pragma unroll
    for (int t = 0; t < 8; t++) {
#pragma unroll
        for (int ks = 0; ks < 2; ks++)
            mma_f16(cu[t][0], cu[t][1], dum0, dum1,
                    aw[ks][0], 0u, aw[ks][1], 0u, tiles[2 * ks][t], tiles[2 * ks + 1][t]);
    }
}

// ---------------- kernel 4: attention + fused slot update (last block per b) ----
// grid: (16, 64), 128 threads = 4 warps; warp = 64 kv rows (2 chunks of 32).
__global__ __launch_bounds__(128, 5) void attn_kernel(
    const float* __restrict__ bih, const float* __restrict__ bhh,
    const float* __restrict__ w1,  const float* __restrict__ b1v,
    const float* __restrict__ w2,  const float* __restrict__ b2v,
    const float* __restrict__ lg,  const float* __restrict__ lb,
    const float* __restrict__ Wq,  float* __restrict__ out)
{
    const int b = blockIdx.y;
    const int tid = threadIdx.x;
    const int w = tid >> 5, l = tid & 31;
    const int s = l >> 2, c = l & 3;

    __shared__ __align__(16) unsigned sK[4 * 1152];
    __shared__ __align__(16) unsigned sV[4 * 1152];
    __shared__ int sLast;
    unsigned* sk = sK + w * 1152;
    unsigned* sv = sV + w * 1152;
    const uint32_t skb = smem_u32(sk);
    const uint32_t svb = smem_u32(sv);

    // q A-fragments (shared by both chunks)
    unsigned aq[4][2];
    {
        const float* qb = g_q + b * 448 + s * 64;
#pragma unroll
        for (int ks = 0; ks < 4; ks++) {
            if (s < 7) {
                float2 f0 = *(const float2*)&qb[ks * 16 + 2 * c];
                float2 f1 = *(const float2*)&qb[ks * 16 + 8 + 2 * c];
                aq[ks][0] = h2(f0.x, f0.y);
                aq[ks][1] = h2(f1.x, f1.y);
            } else { aq[ks][0] = 0u; aq[ks][1] = 0u; }
        }
    }

    const size_t rowbase = (size_t)b * NN + blockIdx.x * 256 + w * 64;
    const uint4* kg = (const uint4*)(g_k + rowbase * 32);
    const uint4* vg = (const uint4*)(g_v + rowbase * 32);

    stage_cp(skb, kg, l);            // G1: K0
    stage_cp(svb, vg, l);            // G2: V0

    unsigned tiles[4][8];
    float cu[8][2];
#pragma unroll
    for (int t = 0; t < 8; t++) { cu[t][0] = 0.f; cu[t][1] = 0.f; }
    float wreg[4][2];
    float dlT = 0.f;

    // ---- chunk 0 ----
    CP_WAIT(1); __syncwarp();
    ldsm_tiles(tiles, skb, l, false);
    stage_cp(skb, kg + 256, l);      // G3: K1
    dlT += softmax_chunk(tiles, aq, wreg, s);
    CP_WAIT(1); __syncwarp();        // V0 ready
    ldsm_tiles(tiles, svb, l, true);
    stage_cp(svb, vg + 256, l);      // G4: V1
    phase2_chunk(tiles, wreg, cu);

    // ---- chunk 1 ----
    CP_WAIT(1); __syncwarp();        // K1 ready
    ldsm_tiles(tiles, skb, l, false);
    dlT += softmax_chunk(tiles, aq, wreg, s);
    CP_WAIT(0); __syncwarp();        // V1 ready
    ldsm_tiles(tiles, svb, l, true);
    phase2_chunk(tiles, wreg, cu);

    // ---- per-warp partials in dead V buffer, tree-reduce, atomics ----
    dlT += __shfl_xor_sync(0xffffffffu, dlT, 1);
    dlT += __shfl_xor_sync(0xffffffffu, dlT, 2);
    float* red_ = (float*)sv;
    if (s < 7) {
#pragma unroll
        for (int t = 0; t < 8; t++)
            *(float2*)&red_[s * 64 + 8 * t + 2 * c] = make_float2(cu[t][0], cu[t][1]);
        if (c == 0) red_[448 + s] = dlT;
    }
    __syncthreads();

    float* pr = (float*)sV;
    for (int i = tid; i < 455; i += 128) {
        float t = pr[i] + pr[1152 + i] + pr[2304 + i] + pr[3456 + i];
        if (i < 448) atomicAdd(&g_numer[b * 448 + i], t);
        else atomicAdd(&g_denom[b * SS + (i - 448)], t);
    }

    // ---- completion: last block of this b performs the slot update ----
    __threadfence();
    __syncthreads();
    if (tid == 0) {
        int old = atomicAdd(&g_cnt[b], 1);
        sLast = (old == 15) ? 1 : 0;
        if (old == 15) g_cnt[b] = 0;      // reset for next launch
    }
    __syncthreads();
    if (!sLast) return;
    __threadfence();                      // acquire: see all blocks' numer atomics

    // ------ inline update for all 7 slots of batch b (128 threads) ------
    const int d = tid & 63, hf = tid >> 6;
    float* fs  = (float*)sK;
    float* su  = fs;          // 64
    float* sh  = fs + 64;     // 64
    float* shn = fs + 128;    // 64
    float* so  = fs + 192;    // 64
    float* smm = fs + 256;    // 128
    float* sp  = fs + 384;    // 6*128
    float* rd  = fs + 1152;   // 4

    for (int s7 = 0; s7 < SS; s7++) {
        const int bs = b * SS + s7;
        if (hf == 0) {
            su[d] = g_numer[bs * 64 + d] / g_denom[bs];
            sh[d] = g_slots[bs * 64 + d];
        }
        __syncthreads();

        float a0 = 0.f, a1 = 0.f, a2 = 0.f, c0 = 0.f, c1 = 0.f, c2 = 0.f;
        const int tbase = hf * 32;
#pragma unroll 8
        for (int i = 0; i < 32; i++) {
            int t = tbase + i;
            float ut = su[t], ht = sh[t];
            const float* wi = &g_wihT[t * 192];
            const float* wh = &g_whhT[t * 192];
            a0 += ut * wi[d]; a1 += ut * wi[64 + d]; a2 += ut * wi[128 + d];
            c0 += ht * wh[d]; c1 += ht * wh[64 + d]; c2 += ht * wh[128 + d];
        }
        sp[0 * 128 + tid] = a0; sp[1 * 128 + tid] = a1; sp[2 * 128 + tid] = a2;
        sp[3 * 128 + tid] = c0; sp[4 * 128 + tid] = c1; sp[5 * 128 + tid] = c2;
        __syncthreads();

        if (hf == 0) {
            float A0 = bih[d]       + sp[0 * 128 + d] + sp[0 * 128 + 64 + d];
            float A1 = bih[64 + d]  + sp[1 * 128 + d] + sp[1 * 128 + 64 + d];
            float A2 = bih[128 + d] + sp[2 * 128 + d] + sp[2 * 128 + 64 + d];
            float C0 = bhh[d]       + sp[3 * 128 + d] + sp[3 * 128 + 64 + d];
            float C1 = bhh[64 + d]  + sp[4 * 128 + d] + sp[4 * 128 + 64 + d];
            float C2 = bhh[128 + d] + sp[5 * 128 + d] + sp[5 * 128 + 64 + d];
            float r = 1.f / (1.f + __expf(-(A0 + C0)));
            float z = 1.f / (1.f + __expf(-(A1 + C1)));
            float n = tanhf(A2 + r * C2);
            shn[d] = (1.f - z) * n + z * sh[d];
        }
        __syncthreads();

        float m = b1v[tid];
#pragma unroll 8
        for (int t = 0; t < 64; t++) m += shn[t] * w1[t * 128 + tid];
        smm[tid] = fmaxf(m, 0.f);
        __syncthreads();

        float op = 0.f;
#pragma unroll 8
        for (int i = 0; i < 64; i++) {
            int cc = hf * 64 + i;
            op += smm[cc] * w2[cc * 64 + d];
        }
        sp[tid] = op;
        __syncthreads();

        if (hf == 0) {
            float oo = shn[d] + b2v[d] + sp[d] + sp[64 + d];
            g_slots[bs * 64 + d] = oo;
            if (out) out[bs * 64 + d] = oo;
            so[d] = oo;
        }
        __syncthreads();

        // LN on new slots
        if (hf == 0) {
            float v = so[d];
            float s1 = v, s2 = v * v;
#pragma unroll
            for (int o = 16; o; o >>= 1) {
                s1 += __shfl_xor_sync(0xffffffffu, s1, o);
                s2 += __shfl_xor_sync(0xffffffffu, s2, o);
            }
            if ((d & 31) == 0) { rd[d >> 5] = s1; rd[2 + (d >> 5)] = s2; }
        }
        __syncthreads();
        if (hf == 0) {
            float S = rd[0] + rd[1], S2 = rd[2] + rd[3];
            float mm = S * 0.015625f;
            float var = fmaxf(S2 * 0.015625f - mm * mm, 0.f);
            float inv = rsqrtf(var + 1e-5f);
            shn[d] = (so[d] - mm) * inv * lg[d] + lb[d];
        }
        __syncthreads();

        float qp = 0.f;
#pragma unroll 8
        for (int i = 0; i < 32; i++) {
            int j = hf * 32 + i;
            qp += shn[j] * Wq[j * 64 + d];
        }
        sp[tid] = qp;
        __syncthreads();

        if (hf == 0) {
            g_q[bs * 64 + d] = (sp[d] + sp[64 + d]) * 0.125f;
            g_numer[bs * 64 + d] = 0.f;
            if (d == 0) g_denom[bs] = 0.f;
        }
        __syncthreads();
    }
}

// ---------------- launch ----------------
extern "C" void kernel_launch(void* const* d_in, const int* in_sizes, int n_in,
                              void* d_out, int out_size) {
    (void)in_sizes; (void)n_in; (void)out_size;
    const float* x          = (const float*)d_in[0];
    const float* ln_inp_g   = (const float*)d_in[1];
    const float* ln_inp_b   = (const float*)d_in[2];
    const float* ln_slot_g  = (const float*)d_in[3];
    const float* ln_slot_b  = (const float*)d_in[4];
    const float* slots_init = (const float*)d_in[5];
    const float* Wk         = (const float*)d_in[6];
    const float* Wv         = (const float*)d_in[7];
    const float* Wq         = (const float*)d_in[8];
    const float* gwih       = (const float*)d_in[9];
    const float* gwhh       = (const float*)d_in[10];
    const float* gbih       = (const float*)d_in[11];
    const float* gbhh       = (const float*)d_in[12];
    const float* w1         = (const float*)d_in[13];
    const float* b1         = (const float*)d_in[14];
    const float* w2         = (const float*)d_in[15];
    const float* b2         = (const float*)d_in[16];
    float* out = (float*)d_out;

    // 4th launch is profiled by ncu -> fused attn this round.
    prep_kernel<<<112, 256>>>(Wk, Wv, gwih, gwhh);                      // 1
    init_kernel<<<BB * SS, 64>>>(slots_init, ln_slot_g, ln_slot_b, Wq); // 2
    proj_kernel<<<(BB * NN) / 128, 256>>>(x, ln_inp_g, ln_inp_b);       // 3
    for (int it = 0; it < 3; it++) {
        attn_kernel<<<dim3(16, BB), 128>>>(gbih, gbhh, w1, b1, w2, b2,
                                           ln_slot_g, ln_slot_b, Wq,
                                           it == 2 ? out : nullptr);    // 4 <- profiled
    }
}

// round 12
// speedup vs baseline: 1.7275x; 1.7275x over previous
#include <cuda_runtime.h>
#include <cstdint>

#define BB 64
#define NN 4096
#define SS 7

// ---------------- scratch (static device globals; no allocation) ----------------
__device__ unsigned g_k[BB * NN * 32];       // f16x2 words: 32 MB
__device__ unsigned g_v[BB * NN * 32];       // 32 MB
__device__ float g_q[BB * 448];              // q [b][s][64] (scaled by 1/8)
__device__ float g_slots[BB * SS * 64];
__device__ float g_numer[BB * 448];
__device__ float g_denom[BB * SS];
__device__ unsigned g_Bt[128 * 32];          // B^T: [n][k] f16x2 words (Wk|Wv)
__device__ float g_wihT[64 * 192];           // GRU weights transposed [t][j]
__device__ float g_whhT[64 * 192];

// ---------------- helpers ----------------
__device__ __forceinline__ unsigned h2(float lo, float hi) {
    unsigned r;
    asm("cvt.rn.f16x2.f32 %0, %1, %2;" : "=r"(r) : "f"(hi), "f"(lo));
    return r;
}
__device__ __forceinline__ uint32_t smem_u32(const void* p) {
    uint32_t a;
    asm("{ .reg .u64 t; cvta.to.shared.u64 t, %1; cvt.u32.u64 %0, t; }" : "=r"(a) : "l"(p));
    return a;
}
__device__ __forceinline__ void mma_f16(float& c0, float& c1, float& c2, float& c3,
                                        unsigned a0, unsigned a1, unsigned a2, unsigned a3,
                                        unsigned b0, unsigned b1) {
    asm volatile(
        "mma.sync.aligned.m16n8k16.row.col.f32.f16.f16.f32 "
        "{%0,%1,%2,%3}, {%4,%5,%6,%7}, {%8,%9}, {%0,%1,%2,%3};"
        : "+f"(c0), "+f"(c1), "+f"(c2), "+f"(c3)
        : "r"(a0), "r"(a1), "r"(a2), "r"(a3), "r"(b0), "r"(b1));
}
#define LDSM4(r0, r1, r2, r3, a) \
    asm volatile("ldmatrix.sync.aligned.m8n8.x4.shared.b16 {%0,%1,%2,%3}, [%4];" \
        : "=r"(r0), "=r"(r1), "=r"(r2), "=r"(r3) : "r"(a))
#define LDSM4T(r0, r1, r2, r3, a) \
    asm volatile("ldmatrix.sync.aligned.m8n8.x4.trans.shared.b16 {%0,%1,%2,%3}, [%4];" \
        : "=r"(r0), "=r"(r1), "=r"(r2), "=r"(r3) : "r"(a))
#define CP16(dst, src) \
    asm volatile("cp.async.ca.shared.global [%0], [%1], 16;" :: "r"(dst), "l"(src))
#define CP_COMMIT() asm volatile("cp.async.commit_group;" ::: "memory")
#define CP_WAIT(n)  asm volatile("cp.async.wait_group %0;" :: "n"(n) : "memory")

// ---------------- common: LN(v over 64) with 2-warp block ----------------------
__device__ __forceinline__ float block_ln64(float v, int d, float* red) {
    float s1 = v, s2 = v * v;
#pragma unroll
    for (int o = 16; o; o >>= 1) {
        s1 += __shfl_xor_sync(0xffffffffu, s1, o);
        s2 += __shfl_xor_sync(0xffffffffu, s2, o);
    }
    const int wd = d >> 5;
    if ((d & 31) == 0) { red[wd] = s1; red[2 + wd] = s2; }
    __syncthreads();
    float S = red[0] + red[1], S2 = red[2] + red[3];
    float m = S * 0.015625f;
    float var = fmaxf(S2 * 0.015625f - m * m, 0.f);
    float inv = rsqrtf(var + 1e-5f);
    return (v - m) * inv;
}

// ---------------- kernel P1: B^T prep ----------------
__global__ void prep1_kernel(const float* __restrict__ Wk, const float* __restrict__ Wv) {
    int i = blockIdx.x * 256 + threadIdx.x;
    if (i < 4096) {
        int n = i >> 5, w = i & 31;
        const float* W = (n < 64) ? Wk : Wv;
        int nc = n & 63;
        g_Bt[i] = h2(W[(2 * w) * 64 + nc], W[(2 * w + 1) * 64 + nc]);
    }
}

// ---------------- kernel P2: GRU weight transposes ----------------
__global__ void prep2_kernel(const float* __restrict__ wih, const float* __restrict__ whh) {
    int i = blockIdx.x * 256 + threadIdx.x;
    if (i < 12288) {
        int t = i / 192, j = i % 192;
        g_wihT[i] = wih[j * 64 + t];
        g_whhT[i] = whh[j * 64 + t];
    }
}

// ---------------- kernel 0: init slots + q0 + zero accumulators -----------------
__global__ __launch_bounds__(64) void init_kernel(
    const float* __restrict__ s0,
    const float* __restrict__ lg, const float* __restrict__ lb,
    const float* __restrict__ Wq)
{
    const int bs = blockIdx.x;
    const int s = bs % SS;
    const int d = threadIdx.x;
    __shared__ float ssn[64];
    __shared__ float red[4];

    float v = s0[s * 64 + d];
    g_slots[bs * 64 + d] = v;

    float sn = block_ln64(v, d, red) * lg[d] + lb[d];
    ssn[d] = sn;
    __syncthreads();

    float q = 0.f;
#pragma unroll 8
    for (int j = 0; j < 64; j++) q += ssn[j] * Wq[j * 64 + d];
    g_q[bs * 64 + d] = q * 0.125f;
    g_numer[bs * 64 + d] = 0.f;
    if (d == 0) g_denom[bs] = 0.f;
}

// ---------------- kernel 1: fused LN + f16 HMMA GEMM -> k|v ---------------------
#define PITCH 36
__global__ __launch_bounds__(256) void proj_kernel(
    const float* __restrict__ x,
    const float* __restrict__ lg, const float* __restrict__ lb)
{
    __shared__ __align__(16) unsigned sA[128 * PITCH];
    __shared__ __align__(16) unsigned sB[128 * PITCH];

    const int tid = threadIdx.x;
    const int w = tid >> 5, lane = tid & 31;
    const int row0 = blockIdx.x * 128;

    // stage B^T via cp.async (overlaps with the x LDGs below)
    const uint32_t sBb = smem_u32(sB);
    {
#pragma unroll
        for (int t = 0; t < 4; t++) {
            int q4 = t * 256 + tid;               // 16B unit index (1024 total)
            int n = q4 >> 3, m = q4 & 7;          // row n, word-group m
            CP16(sBb + (n * PITCH + m * 4) * 4, (const uint4*)g_Bt + q4);
        }
        CP_COMMIT();
    }

    const float4* x4 = (const float4*)(x + (size_t)row0 * 64);
    float4 f[8];
#pragma unroll
    for (int t = 0; t < 8; t++) f[t] = x4[t * 256 + tid];

    {
        const int j = tid & 15;
        const float4 gg = ((const float4*)lg)[j];
        const float4 bb = ((const float4*)lb)[j];
#pragma unroll
        for (int t = 0; t < 8; t++) {
            float4 v = f[t];
            float s1 = v.x + v.y + v.z + v.w;
            float s2 = v.x * v.x + v.y * v.y + v.z * v.z + v.w * v.w;
#pragma unroll
            for (int o = 1; o <= 8; o <<= 1) {
                s1 += __shfl_xor_sync(0xffffffffu, s1, o);
                s2 += __shfl_xor_sync(0xffffffffu, s2, o);
            }
            float m = s1 * 0.015625f;
            float var = fmaxf(s2 * 0.015625f - m * m, 0.f);
            float inv = rsqrtf(var + 1e-5f);
            float y0 = (v.x - m) * inv * gg.x + bb.x;
            float y1 = (v.y - m) * inv * gg.y + bb.y;
            float y2 = (v.z - m) * inv * gg.z + bb.z;
            float y3 = (v.w - m) * inv * gg.w + bb.w;
            int row = t * 16 + (tid >> 4);
            *(uint2*)&sA[row * PITCH + j * 2] = make_uint2(h2(y0, y1), h2(y2, y3));
        }
    }
    CP_WAIT(0);
    __syncthreads();

    const int r0 = w * 16;
    const int qr = lane >> 2, qc = lane & 3;
    const int ra = r0 + qr, rb = ra + 8;

    unsigned afr[4][4];
#pragma unroll
    for (int ks = 0; ks < 4; ks++) {
        afr[ks][0] = sA[ra * PITCH + qc + ks * 8];
        afr[ks][1] = sA[rb * PITCH + qc + ks * 8];
        afr[ks][2] = sA[ra * PITCH + qc + 4 + ks * 8];
        afr[ks][3] = sA[rb * PITCH + qc + 4 + ks * 8];
    }
    __syncthreads();

    // B-fragment ldmatrix base (validated in R11): rows n8+(lane&7),
    // word offset = ((lane>>3)&1)*4 + (lane>>4)*8.
    const uint32_t bB = sBb + ((((lane & 7)) * PITCH + ((lane >> 3) & 1) * 4 + (lane >> 4) * 8) << 2);

#pragma unroll
    for (int pass = 0; pass < 2; pass++) {
#pragma unroll
        for (int b8 = 0; b8 < 8; b8++) {
            float c0 = 0.f, c1 = 0.f, c2 = 0.f, c3 = 0.f;
            const uint32_t a0 = bB + (((pass * 8 + b8) * 8 * PITCH) << 2);
            unsigned q0, q1, q2, q3;
            LDSM4(q0, q1, q2, q3, a0);          // (ks0 b0, ks0 b1, ks1 b0, ks1 b1)
            mma_f16(c0, c1, c2, c3, afr[0][0], afr[0][1], afr[0][2], afr[0][3], q0, q1);
            mma_f16(c0, c1, c2, c3, afr[1][0], afr[1][1], afr[1][2], afr[1][3], q2, q3);
            LDSM4(q0, q1, q2, q3, a0 + 64);     // (ks2 b0, ks2 b1, ks3 b0, ks3 b1)
            mma_f16(c0, c1, c2, c3, afr[2][0], afr[2][1], afr[2][2], afr[2][3], q0, q1);
            mma_f16(c0, c1, c2, c3, afr[3][0], afr[3][1], afr[3][2], afr[3][3], q2, q3);
            sA[ra * PITCH + b8 * 4 + qc] = h2(c0, c1);
            sA[rb * PITCH + b8 * 4 + qc] = h2(c2, c3);
        }
        __syncthreads();
        unsigned* dst = pass ? g_v : g_k;
#pragma unroll
        for (int p = 0; p < 4; p++) {
            int row = p * 32 + (tid >> 3);
            uint4 val = *(uint4*)&sA[row * PITCH + (tid & 7) * 4];
            *(uint4*)&dst[(size_t)(row0 + row) * 32 + (tid & 7) * 4] = val;
        }
        __syncthreads();
    }
}

// ---------------- attn helpers ----------------
__device__ __forceinline__ void stage_cp(uint32_t base, const uint4* g, int l) {
    const uint32_t off = (((l >> 3)) * 36 + (l & 7) * 4) << 2;
#pragma unroll
    for (int i = 0; i < 8; i++)
        CP16(base + off + i * 576, g + i * 32 + l);
    CP_COMMIT();
}
__device__ __forceinline__ void ldsm_tiles(unsigned t[4][8], uint32_t base, int l, bool trans) {
#pragma unroll
    for (int g = 0; g < 4; g++)
#pragma unroll
        for (int cc = 0; cc < 2; cc++) {
            uint32_t a = base + (((8 * g + (l & 7)) * 36 + (4 * cc + (l >> 3)) * 4) << 2);
            if (trans) LDSM4T(t[g][4 * cc], t[g][4 * cc + 1], t[g][4 * cc + 2], t[g][4 * cc + 3], a);
            else       LDSM4 (t[g][4 * cc], t[g][4 * cc + 1], t[g][4 * cc + 2], t[g][4 * cc + 3], a);
        }
}
__device__ __forceinline__ float softmax_chunk(unsigned tiles[4][8], unsigned aq[4][2],
                                               float wreg[4][2], int s) {
    float dum0 = 0.f, dum1 = 0.f;
    float cl[4][2];
#pragma unroll
    for (int g = 0; g < 4; g++) {
        cl[g][0] = 0.f; cl[g][1] = 0.f;
#pragma unroll
        for (int ks = 0; ks < 4; ks++)
            mma_f16(cl[g][0], cl[g][1], dum0, dum1,
                    aq[ks][0], 0u, aq[ks][1], 0u, tiles[g][2 * ks], tiles[g][2 * ks + 1]);
    }
    float dl = 0.f;
#pragma unroll
    for (int g = 0; g < 4; g++) {
        float x0 = (s < 7) ? cl[g][0] : -1e30f;
        float x1 = (s < 7) ? cl[g][1] : -1e30f;
        float m0 = x0, m1 = x1;
#pragma unroll
        for (int o = 4; o <= 16; o <<= 1) {
            m0 = fmaxf(m0, __shfl_xor_sync(0xffffffffu, m0, o));
            m1 = fmaxf(m1, __shfl_xor_sync(0xffffffffu, m1, o));
        }
        float e0 = __expf(x0 - m0), e1 = __expf(x1 - m1);
        float t0 = e0, t1 = e1;
#pragma unroll
        for (int o = 4; o <= 16; o <<= 1) {
            t0 += __shfl_xor_sync(0xffffffffu, t0, o);
            t1 += __shfl_xor_sync(0xffffffffu, t1, o);
        }
        float w0 = (s < 7) ? e0 / t0 + 1e-8f : 0.f;
        float w1 = (s < 7) ? e1 / t1 + 1e-8f : 0.f;
        dl += w0 + w1;
        wreg[g][0] = w0; wreg[g][1] = w1;
    }
    return dl;
}
__device__ __forceinline__ void phase2_chunk(unsigned tiles[4][8], float wreg[4][2],
                                             float cu[8][2]) {
    float dum0 = 0.f, dum1 = 0.f;
    unsigned aw[2][2];
    aw[0][0] = h2(wreg[0][0], wreg[0][1]);
    aw[0][1] = h2(wreg[1][0], wreg[1][1]);
    aw[1][0] = h2(wreg[2][0], wreg[2][1]);
    aw[1][1] = h2(wreg[3][0], wreg[3][1]);
#pragma unroll
    for (int t = 0; t < 8; t++) {
#pragma unroll
        for (int ks = 0; ks < 2; ks++)
            mma_f16(cu[t][0], cu[t][1], dum0, dum1,
                    aw[ks][0], 0u, aw[ks][1], 0u, tiles[2 * ks][t], tiles[2 * ks + 1][t]);
    }
}

// ---------------- kernel 4: attention (64 rows/warp, cp.async pipeline) ---------
__global__ __launch_bounds__(128, 5) void attn_kernel() {
    const int b = blockIdx.y;
    const int w = threadIdx.x >> 5, l = threadIdx.x & 31;
    const int s = l >> 2, c = l & 3;

    __shared__ __align__(16) unsigned sK[4 * 1152];
    __shared__ __align__(16) unsigned sV[4 * 1152];
    unsigned* sk = sK + w * 1152;
    unsigned* sv = sV + w * 1152;
    const uint32_t skb = smem_u32(sk);
    const uint32_t svb = smem_u32(sv);

    // q A-fragments (shared by both chunks)
    unsigned aq[4][2];
    {
        const float* qb = g_q + b * 448 + s * 64;
#pragma unroll
        for (int ks = 0; ks < 4; ks++) {
            if (s < 7) {
                float2 f0 = *(const float2*)&qb[ks * 16 + 2 * c];
                float2 f1 = *(const float2*)&qb[ks * 16 + 8 + 2 * c];
                aq[ks][0] = h2(f0.x, f0.y);
                aq[ks][1] = h2(f1.x, f1.y);
            } else { aq[ks][0] = 0u; aq[ks][1] = 0u; }
        }
    }

    const size_t rowbase = (size_t)b * NN + blockIdx.x * 256 + w * 64;
    const uint4* kg = (const uint4*)(g_k + rowbase * 32);
    const uint4* vg = (const uint4*)(g_v + rowbase * 32);

    stage_cp(skb, kg, l);            // G1: K0
    stage_cp(svb, vg, l);            // G2: V0

    unsigned tiles[4][8];
    float cu[8][2];
#pragma unroll
    for (int t = 0; t < 8; t++) { cu[t][0] = 0.f; cu[t][1] = 0.f; }
    float wreg[4][2];
    float dlT = 0.f;

    // ---- chunk 0 ----
    CP_WAIT(1); __syncwarp();
    ldsm_tiles(tiles, skb, l, false);
    stage_cp(skb, kg + 256, l);      // G3: K1
    dlT += softmax_chunk(tiles, aq, wreg, s);
    CP_WAIT(1); __syncwarp();        // V0 ready
    ldsm_tiles(tiles, svb, l, true);
    stage_cp(svb, vg + 256, l);      // G4: V1
    phase2_chunk(tiles, wreg, cu);

    // ---- chunk 1 ----
    CP_WAIT(1); __syncwarp();        // K1 ready
    ldsm_tiles(tiles, skb, l, false);
    dlT += softmax_chunk(tiles, aq, wreg, s);
    CP_WAIT(0); __syncwarp();        // V1 ready
    ldsm_tiles(tiles, svb, l, true);
    phase2_chunk(tiles, wreg, cu);

    // ---- per-warp partials in dead V buffer, tree-reduce, atomics ----
    dlT += __shfl_xor_sync(0xffffffffu, dlT, 1);
    dlT += __shfl_xor_sync(0xffffffffu, dlT, 2);
    float* red = (float*)sv;
    if (s < 7) {
#pragma unroll
        for (int t = 0; t < 8; t++)
            *(float2*)&red[s * 64 + 8 * t + 2 * c] = make_float2(cu[t][0], cu[t][1]);
        if (c == 0) red[448 + s] = dlT;
    }
    __syncthreads();

    float* pr = (float*)sV;
    for (int i = threadIdx.x; i < 455; i += 128) {
        float t = pr[i] + pr[1152 + i] + pr[2304 + i] + pr[3456 + i];
        if (i < 448) atomicAdd(&g_numer[b * 448 + i], t);
        else atomicAdd(&g_denom[b * SS + (i - 448)], t);
    }
}

// ---------------- kernel 5: updates -> GRU -> MLP -> slots -> q(next) ----------
// grid: 448 blocks x 128 threads; t-loops split across half-threadsets.
__global__ __launch_bounds__(128) void update_kernel(
    const float* __restrict__ bih, const float* __restrict__ bhh,
    const float* __restrict__ w1,  const float* __restrict__ b1v,
    const float* __restrict__ w2,  const float* __restrict__ b2v,
    const float* __restrict__ lg,  const float* __restrict__ lb,
    const float* __restrict__ Wq,  float* __restrict__ out)
{
    const int bs = blockIdx.x;
    const int tid = threadIdx.x;
    const int d = tid & 63, hf = tid >> 6;

    __shared__ float su[64], sh[64], shn[64], so[64], smm[128];
    __shared__ float sp[6][128];
    __shared__ float red[4];

    if (hf == 0) {
        float den = g_denom[bs];
        su[d] = g_numer[bs * 64 + d] / den;
        sh[d] = g_slots[bs * 64 + d];
    }
    __syncthreads();

    float a0 = 0.f, a1 = 0.f, a2 = 0.f, c0 = 0.f, c1 = 0.f, c2 = 0.f;
    const int tbase = hf * 32;
#pragma unroll 8
    for (int i = 0; i < 32; i++) {
        int t = tbase + i;
        float ut = su[t], ht = sh[t];
        const float* wi = &g_wihT[t * 192];
        const float* wh = &g_whhT[t * 192];
        a0 += ut * wi[d]; a1 += ut * wi[64 + d]; a2 += ut * wi[128 + d];
        c0 += ht * wh[d]; c1 += ht * wh[64 + d]; c2 += ht * wh[128 + d];
    }
    sp[0][tid] = a0; sp[1][tid] = a1; sp[2][tid] = a2;
    sp[3][tid] = c0; sp[4][tid] = c1; sp[5][tid] = c2;
    __syncthreads();

    if (hf == 0) {
        float A0 = bih[d]       + sp[0][d] + sp[0][64 + d];
        float A1 = bih[64 + d]  + sp[1][d] + sp[1][64 + d];
        float A2 = bih[128 + d] + sp[2][d] + sp[2][64 + d];
        float C0 = bhh[d]       + sp[3][d] + sp[3][64 + d];
        float C1 = bhh[64 + d]  + sp[4][d] + sp[4][64 + d];
        float C2 = bhh[128 + d] + sp[5][d] + sp[5][64 + d];
        float r = 1.f / (1.f + __expf(-(A0 + C0)));
        float z = 1.f / (1.f + __expf(-(A1 + C1)));
        float n = tanhf(A2 + r * C2);
        shn[d] = (1.f - z) * n + z * sh[d];
    }
    __syncthreads();

    float m = b1v[tid];
#pragma unroll 8
    for (int t = 0; t < 64; t++) m += shn[t] * w1[t * 128 + tid];
    smm[tid] = fmaxf(m, 0.f);
    __syncthreads();

    float op = 0.f;
#pragma unroll 8
    for (int i = 0; i < 64; i++) {
        int cc = hf * 64 + i;
        op += smm[cc] * w2[cc * 64 + d];
    }
    sp[0][tid] = op;
    __syncthreads();

    if (hf == 0) {
        float oo = shn[d] + b2v[d] + sp[0][d] + sp[0][64 + d];
        g_slots[bs * 64 + d] = oo;
        if (out) out[bs * 64 + d] = oo;
        so[d] = oo;
    }
    __syncthreads();

    if (hf == 0) {
        float v = so[d];
        float s1 = v, s2 = v * v;
#pragma unroll
        for (int o = 16; o; o >>= 1) {
            s1 += __shfl_xor_sync(0xffffffffu, s1, o);
            s2 += __shfl_xor_sync(0xffffffffu, s2, o);
        }
        if ((d & 31) == 0) { red[d >> 5] = s1; red[2 + (d >> 5)] = s2; }
    }
    __syncthreads();
    if (hf == 0) {
        float S = red[0] + red[1], S2 = red[2] + red[3];
        float mm = S * 0.015625f;
        float var = fmaxf(S2 * 0.015625f - mm * mm, 0.f);
        float inv = rsqrtf(var + 1e-5f);
        shn[d] = (so[d] - mm) * inv * lg[d] + lb[d];
    }
    __syncthreads();

    float qp = 0.f;
#pragma unroll 8
    for (int i = 0; i < 32; i++) {
        int j = hf * 32 + i;
        qp += shn[j] * Wq[j * 64 + d];
    }
    sp[0][tid] = qp;
    __syncthreads();

    if (hf == 0) {
        g_q[bs * 64 + d] = (sp[0][d] + sp[0][64 + d]) * 0.125f;
        g_numer[bs * 64 + d] = 0.f;
        if (d == 0) g_denom[bs] = 0.f;
    }
}

// ---------------- launch ----------------
extern "C" void kernel_launch(void* const* d_in, const int* in_sizes, int n_in,
                              void* d_out, int out_size) {
    (void)in_sizes; (void)n_in; (void)out_size;
    const float* x          = (const float*)d_in[0];
    const float* ln_inp_g   = (const float*)d_in[1];
    const float* ln_inp_b   = (const float*)d_in[2];
    const float* ln_slot_g  = (const float*)d_in[3];
    const float* ln_slot_b  = (const float*)d_in[4];
    const float* slots_init = (const float*)d_in[5];
    const float* Wk         = (const float*)d_in[6];
    const float* Wv         = (const float*)d_in[7];
    const float* Wq         = (const float*)d_in[8];
    const float* gwih       = (const float*)d_in[9];
    const float* gwhh       = (const float*)d_in[10];
    const float* gbih       = (const float*)d_in[11];
    const float* gbhh       = (const float*)d_in[12];
    const float* w1         = (const float*)d_in[13];
    const float* b1         = (const float*)d_in[14];
    const float* w2         = (const float*)d_in[15];
    const float* b2         = (const float*)d_in[16];
    float* out = (float*)d_out;

    // 4th launch is profiled by ncu -> proj (measuring the ldmatrix-B change).
    prep1_kernel<<<16, 256>>>(Wk, Wv);                                  // 1
    prep2_kernel<<<48, 256>>>(gwih, gwhh);                              // 2
    init_kernel<<<BB * SS, 64>>>(slots_init, ln_slot_g, ln_slot_b, Wq); // 3
    proj_kernel<<<(BB * NN) / 128, 256>>>(x, ln_inp_g, ln_inp_b);       // 4 <- profiled
    for (int it = 0; it < 3; it++) {
        attn_kernel<<<dim3(16, BB), 128>>>();
        update_kernel<<<BB * SS, 128>>>(gbih, gbhh, w1, b1, w2, b2,
                                        ln_slot_g, ln_slot_b, Wq,
                                        it == 2 ? out : nullptr);
    }
}

// round 13
// speedup vs baseline: 1.8011x; 1.0426x over previous
#include <cuda_runtime.h>
#include <cstdint>

#define BB 64
#define NN 4096
#define SS 7

// ---------------- scratch (static device globals; no allocation) ----------------
__device__ unsigned g_k[BB * NN * 32];       // f16x2 words: 32 MB
__device__ unsigned g_v[BB * NN * 32];       // 32 MB
__device__ float g_q[BB * 448];              // q [b][s][64] (scaled by 1/8)
__device__ float g_slots[BB * SS * 64];
__device__ float g_numer[BB * 448];
__device__ float g_denom[BB * SS];
__device__ unsigned g_Bt[128 * 32];          // B^T: [n][k] f16x2 words (Wk|Wv)
__device__ float g_wihT[64 * 192];           // GRU weights transposed [t][j]
__device__ float g_whhT[64 * 192];

// ---------------- helpers ----------------
__device__ __forceinline__ unsigned h2(float lo, float hi) {
    unsigned r;
    asm("cvt.rn.f16x2.f32 %0, %1, %2;" : "=r"(r) : "f"(hi), "f"(lo));
    return r;
}
__device__ __forceinline__ uint32_t smem_u32(const void* p) {
    uint32_t a;
    asm("{ .reg .u64 t; cvta.to.shared.u64 t, %1; cvt.u32.u64 %0, t; }" : "=r"(a) : "l"(p));
    return a;
}
__device__ __forceinline__ void mma_f16(float& c0, float& c1, float& c2, float& c3,
                                        unsigned a0, unsigned a1, unsigned a2, unsigned a3,
                                        unsigned b0, unsigned b1) {
    asm volatile(
        "mma.sync.aligned.m16n8k16.row.col.f32.f16.f16.f32 "
        "{%0,%1,%2,%3}, {%4,%5,%6,%7}, {%8,%9}, {%0,%1,%2,%3};"
        : "+f"(c0), "+f"(c1), "+f"(c2), "+f"(c3)
        : "r"(a0), "r"(a1), "r"(a2), "r"(a3), "r"(b0), "r"(b1));
}
#define LDSM4(r0, r1, r2, r3, a) \
    asm volatile("ldmatrix.sync.aligned.m8n8.x4.shared.b16 {%0,%1,%2,%3}, [%4];" \
        : "=r"(r0), "=r"(r1), "=r"(r2), "=r"(r3) : "r"(a))
#define LDSM4T(r0, r1, r2, r3, a) \
    asm volatile("ldmatrix.sync.aligned.m8n8.x4.trans.shared.b16 {%0,%1,%2,%3}, [%4];" \
        : "=r"(r0), "=r"(r1), "=r"(r2), "=r"(r3) : "r"(a))
#define CP16(dst, src) \
    asm volatile("cp.async.ca.shared.global [%0], [%1], 16;" :: "r"(dst), "l"(src))
#define CP_COMMIT() asm volatile("cp.async.commit_group;" ::: "memory")
#define CP_WAIT(n)  asm volatile("cp.async.wait_group %0;" :: "n"(n) : "memory")

// ---------------- common: LN(v over 64) with 2-warp block ----------------------
__device__ __forceinline__ float block_ln64(float v, int d, float* red) {
    float s1 = v, s2 = v * v;
#pragma unroll
    for (int o = 16; o; o >>= 1) {
        s1 += __shfl_xor_sync(0xffffffffu, s1, o);
        s2 += __shfl_xor_sync(0xffffffffu, s2, o);
    }
    const int wd = d >> 5;
    if ((d & 31) == 0) { red[wd] = s1; red[2 + wd] = s2; }
    __syncthreads();
    float S = red[0] + red[1], S2 = red[2] + red[3];
    float m = S * 0.015625f;
    float var = fmaxf(S2 * 0.015625f - m * m, 0.f);
    float inv = rsqrtf(var + 1e-5f);
    return (v - m) * inv;
}

// ---------------- kernel 0: init slots/q0/zero + ALL weight prep ----------------
// grid: 448 blocks x 64 threads; gi = bs*64+d covers exactly [0, 28672).
__global__ __launch_bounds__(64) void init_kernel(
    const float* __restrict__ s0,
    const float* __restrict__ lg, const float* __restrict__ lb,
    const float* __restrict__ Wq,
    const float* __restrict__ Wk, const float* __restrict__ Wv,
    const float* __restrict__ wih, const float* __restrict__ whh)
{
    const int bs = blockIdx.x;
    const int s = bs % SS;
    const int d = threadIdx.x;
    __shared__ float ssn[64];
    __shared__ float red[4];

    // ---- weight prep (spread across the whole grid) ----
    const int gi = bs * 64 + d;
    if (gi < 4096) {
        int n = gi >> 5, w = gi & 31;
        const float* W = (n < 64) ? Wk : Wv;
        int nc = n & 63;
        g_Bt[gi] = h2(W[(2 * w) * 64 + nc], W[(2 * w + 1) * 64 + nc]);
    } else if (gi < 16384) {
        int m = gi - 4096;
        int t = m / 192, j = m % 192;
        g_wihT[m] = wih[j * 64 + t];
    } else {
        int m = gi - 16384;
        int t = m / 192, j = m % 192;
        g_whhT[m] = whh[j * 64 + t];
    }

    // ---- slots / q0 / accumulator zeros ----
    float v = s0[s * 64 + d];
    g_slots[bs * 64 + d] = v;

    float sn = block_ln64(v, d, red) * lg[d] + lb[d];
    ssn[d] = sn;
    __syncthreads();

    float q = 0.f;
#pragma unroll 8
    for (int j = 0; j < 64; j++) q += ssn[j] * Wq[j * 64 + d];
    g_q[bs * 64 + d] = q * 0.125f;
    g_numer[bs * 64 + d] = 0.f;
    if (d == 0) g_denom[bs] = 0.f;
}

// ---------------- kernel 1: fused LN + f16 HMMA GEMM -> k|v ---------------------
#define PITCH 36
__global__ __launch_bounds__(256) void proj_kernel(
    const float* __restrict__ x,
    const float* __restrict__ lg, const float* __restrict__ lb)
{
    __shared__ __align__(16) unsigned sA[128 * PITCH];
    __shared__ __align__(16) unsigned sB[128 * PITCH];

    const int tid = threadIdx.x;
    const int w = tid >> 5, lane = tid & 31;
    const int row0 = blockIdx.x * 128;

    // stage B^T via cp.async (overlaps with the x LDGs below)
    const uint32_t sBb = smem_u32(sB);
    {
#pragma unroll
        for (int t = 0; t < 4; t++) {
            int q4 = t * 256 + tid;               // 16B unit index (1024 total)
            int n = q4 >> 3, m = q4 & 7;          // row n, word-group m
            CP16(sBb + (n * PITCH + m * 4) * 4, (const uint4*)g_Bt + q4);
        }
        CP_COMMIT();
    }

    const float4* x4 = (const float4*)(x + (size_t)row0 * 64);
    float4 f[8];
#pragma unroll
    for (int t = 0; t < 8; t++) f[t] = x4[t * 256 + tid];

    {
        const int j = tid & 15;
        const float4 gg = ((const float4*)lg)[j];
        const float4 bb = ((const float4*)lb)[j];
#pragma unroll
        for (int t = 0; t < 8; t++) {
            float4 v = f[t];
            float s1 = v.x + v.y + v.z + v.w;
            float s2 = v.x * v.x + v.y * v.y + v.z * v.z + v.w * v.w;
#pragma unroll
            for (int o = 1; o <= 8; o <<= 1) {
                s1 += __shfl_xor_sync(0xffffffffu, s1, o);
                s2 += __shfl_xor_sync(0xffffffffu, s2, o);
            }
            float m = s1 * 0.015625f;
            float var = fmaxf(s2 * 0.015625f - m * m, 0.f);
            float inv = rsqrtf(var + 1e-5f);
            float y0 = (v.x - m) * inv * gg.x + bb.x;
            float y1 = (v.y - m) * inv * gg.y + bb.y;
            float y2 = (v.z - m) * inv * gg.z + bb.z;
            float y3 = (v.w - m) * inv * gg.w + bb.w;
            int row = t * 16 + (tid >> 4);
            *(uint2*)&sA[row * PITCH + j * 2] = make_uint2(h2(y0, y1), h2(y2, y3));
        }
    }
    CP_WAIT(0);
    __syncthreads();

    const int r0 = w * 16;
    const int qr = lane >> 2, qc = lane & 3;
    const int ra = r0 + qr, rb = ra + 8;

    // A-fragments via ldmatrix: lane l -> row r0 + ((l>>3)&1)*8 + (l&7),
    // word offset (l>>4)*4 (+ ks*8 at use). (a0..a3) order matches mma A operand.
    unsigned afr[4][4];
    {
        const uint32_t aA = smem_u32(sA) +
            (((r0 + ((lane >> 3) & 1) * 8 + (lane & 7)) * PITCH + (lane >> 4) * 4) << 2);
#pragma unroll
        for (int ks = 0; ks < 4; ks++)
            LDSM4(afr[ks][0], afr[ks][1], afr[ks][2], afr[ks][3], aA + (ks * 8 << 2));
    }
    __syncthreads();

    // B-fragment ldmatrix base (validated): rows n8+(lane&7),
    // word offset = ((lane>>3)&1)*4 + (lane>>4)*8.
    const uint32_t bB = sBb + ((((lane & 7)) * PITCH + ((lane >> 3) & 1) * 4 + (lane >> 4) * 8) << 2);

#pragma unroll
    for (int pass = 0; pass < 2; pass++) {
#pragma unroll
        for (int b8 = 0; b8 < 8; b8++) {
            float c0 = 0.f, c1 = 0.f, c2 = 0.f, c3 = 0.f;
            const uint32_t a0 = bB + (((pass * 8 + b8) * 8 * PITCH) << 2);
            unsigned q0, q1, q2, q3;
            LDSM4(q0, q1, q2, q3, a0);          // (ks0 b0, ks0 b1, ks1 b0, ks1 b1)
            mma_f16(c0, c1, c2, c3, afr[0][0], afr[0][1], afr[0][2], afr[0][3], q0, q1);
            mma_f16(c0, c1, c2, c3, afr[1][0], afr[1][1], afr[1][2], afr[1][3], q2, q3);
            LDSM4(q0, q1, q2, q3, a0 + 64);     // (ks2 b0, ks2 b1, ks3 b0, ks3 b1)
            mma_f16(c0, c1, c2, c3, afr[2][0], afr[2][1], afr[2][2], afr[2][3], q0, q1);
            mma_f16(c0, c1, c2, c3, afr[3][0], afr[3][1], afr[3][2], afr[3][3], q2, q3);
            sA[ra * PITCH + b8 * 4 + qc] = h2(c0, c1);
            sA[rb * PITCH + b8 * 4 + qc] = h2(c2, c3);
        }
        __syncthreads();
        unsigned* dst = pass ? g_v : g_k;
#pragma unroll
        for (int p = 0; p < 4; p++) {
            int row = p * 32 + (tid >> 3);
            uint4 val = *(uint4*)&sA[row * PITCH + (tid & 7) * 4];
            *(uint4*)&dst[(size_t)(row0 + row) * 32 + (tid & 7) * 4] = val;
        }
        __syncthreads();
    }
}

// ---------------- attn helpers ----------------
__device__ __forceinline__ void stage_cp(uint32_t base, const uint4* g, int l) {
    const uint32_t off = (((l >> 3)) * 36 + (l & 7) * 4) << 2;
#pragma unroll
    for (int i = 0; i < 8; i++)
        CP16(base + off + i * 576, g + i * 32 + l);
    CP_COMMIT();
}
__device__ __forceinline__ void ldsm_tiles(unsigned t[4][8], uint32_t base, int l, bool trans) {
#pragma unroll
    for (int g = 0; g < 4; g++)
#pragma unroll
        for (int cc = 0; cc < 2; cc++) {
            uint32_t a = base + (((8 * g + (l & 7)) * 36 + (4 * cc + (l >> 3)) * 4) << 2);
            if (trans) LDSM4T(t[g][4 * cc], t[g][4 * cc + 1], t[g][4 * cc + 2], t[g][4 * cc + 3], a);
            else       LDSM4 (t[g][4 * cc], t[g][4 * cc + 1], t[g][4 * cc + 2], t[g][4 * cc + 3], a);
        }
}
__device__ __forceinline__ float softmax_chunk(unsigned tiles[4][8], unsigned aq[4][2],
                                               float wreg[4][2], int s) {
    float dum0 = 0.f, dum1 = 0.f;
    float cl[4][2];
#pragma unroll
    for (int g = 0; g < 4; g++) {
        cl[g][0] = 0.f; cl[g][1] = 0.f;
#pragma unroll
        for (int ks = 0; ks < 4; ks++)
            mma_f16(cl[g][0], cl[g][1], dum0, dum1,
                    aq[ks][0], 0u, aq[ks][1], 0u, tiles[g][2 * ks], tiles[g][2 * ks + 1]);
    }
    float dl = 0.f;
#pragma unroll
    for (int g = 0; g < 4; g++) {
        float x0 = (s < 7) ? cl[g][0] : -1e30f;
        float x1 = (s < 7) ? cl[g][1] : -1e30f;
        float m0 = x0, m1 = x1;
#pragma unroll
        for (int o = 4; o <= 16; o <<= 1) {
            m0 = fmaxf(m0, __shfl_xor_sync(0xffffffffu, m0, o));
            m1 = fmaxf(m1, __shfl_xor_sync(0xffffffffu, m1, o));
        }
        float e0 = __expf(x0 - m0), e1 = __expf(x1 - m1);
        float t0 = e0, t1 = e1;
#pragma unroll
        for (int o = 4; o <= 16; o <<= 1) {
            t0 += __shfl_xor_sync(0xffffffffu, t0, o);
            t1 += __shfl_xor_sync(0xffffffffu, t1, o);
        }
        float w0 = (s < 7) ? e0 / t0 + 1e-8f : 0.f;
        float w1 = (s < 7) ? e1 / t1 + 1e-8f : 0.f;
        dl += w0 + w1;
        wreg[g][0] = w0; wreg[g][1] = w1;
    }
    return dl;
}
__device__ __forceinline__ void phase2_chunk(unsigned tiles[4][8], float wreg[4][2],
                                             float cu[8][2]) {
    float dum0 = 0.f, dum1 = 0.f;
    unsigned aw[2][2];
    aw[0][0] = h2(wreg[0][0], wreg[0][1]);
    aw[0][1] = h2(wreg[1][0], wreg[1][1]);
    aw[1][0] = h2(wreg[2][0], wreg[2][1]);
    aw[1][1] = h2(wreg[3][0], wreg[3][1]);
#pragma unroll
    for (int t = 0; t < 8; t++) {
#pragma unroll
        for (int ks = 0; ks < 2; ks++)
            mma_f16(cu[t][0], cu[t][1], dum0, dum1,
                    aw[ks][0], 0u, aw[ks][1], 0u, tiles[2 * ks][t], tiles[2 * ks + 1][t]);
    }
}

// ---------------- kernel 4: attention (64 rows/warp, cp.async pipeline) ---------
__global__ __launch_bounds__(128, 5) void attn_kernel() {
    const int b = blockIdx.y;
    const int w = threadIdx.x >> 5, l = threadIdx.x & 31;
    const int s = l >> 2, c = l & 3;

    __shared__ __align__(16) unsigned sK[4 * 1152];
    __shared__ __align__(16) unsigned sV[4 * 1152];
    unsigned* sk = sK + w * 1152;
    unsigned* sv = sV + w * 1152;
    const uint32_t skb = smem_u32(sk);
    const uint32_t svb = smem_u32(sv);

    // q A-fragments (shared by both chunks)
    unsigned aq[4][2];
    {
        const float* qb = g_q + b * 448 + s * 64;
#pragma unroll
        for (int ks = 0; ks < 4; ks++) {
            if (s < 7) {
                float2 f0 = *(const float2*)&qb[ks * 16 + 2 * c];
                float2 f1 = *(const float2*)&qb[ks * 16 + 8 + 2 * c];
                aq[ks][0] = h2(f0.x, f0.y);
                aq[ks][1] = h2(f1.x, f1.y);
            } else { aq[ks][0] = 0u; aq[ks][1] = 0u; }
        }
    }

    const size_t rowbase = (size_t)b * NN + blockIdx.x * 256 + w * 64;
    const uint4* kg = (const uint4*)(g_k + rowbase * 32);
    const uint4* vg = (const uint4*)(g_v + rowbase * 32);

    stage_cp(skb, kg, l);            // G1: K0
    stage_cp(svb, vg, l);            // G2: V0

    unsigned tiles[4][8];
    float cu[8][2];
#pragma unroll
    for (int t = 0; t < 8; t++) { cu[t][0] = 0.f; cu[t][1] = 0.f; }
    float wreg[4][2];
    float dlT = 0.f;

    // ---- chunk 0 ----
    CP_WAIT(1); __syncwarp();
    ldsm_tiles(tiles, skb, l, false);
    stage_cp(skb, kg + 256, l);      // G3: K1
    dlT += softmax_chunk(tiles, aq, wreg, s);
    CP_WAIT(1); __syncwarp();        // V0 ready
    ldsm_tiles(tiles, svb, l, true);
    stage_cp(svb, vg + 256, l);      // G4: V1
    phase2_chunk(tiles, wreg, cu);

    // ---- chunk 1 ----
    CP_WAIT(1); __syncwarp();        // K1 ready
    ldsm_tiles(tiles, skb, l, false);
    dlT += softmax_chunk(tiles, aq, wreg, s);
    CP_WAIT(0); __syncwarp();        // V1 ready
    ldsm_tiles(tiles, svb, l, true);
    phase2_chunk(tiles, wreg, cu);

    // ---- per-warp partials in dead V buffer, tree-reduce, atomics ----
    dlT += __shfl_xor_sync(0xffffffffu, dlT, 1);
    dlT += __shfl_xor_sync(0xffffffffu, dlT, 2);
    float* red = (float*)sv;
    if (s < 7) {
#pragma unroll
        for (int t = 0; t < 8; t++)
            *(float2*)&red[s * 64 + 8 * t + 2 * c] = make_float2(cu[t][0], cu[t][1]);
        if (c == 0) red[448 + s] = dlT;
    }
    __syncthreads();

    float* pr = (float*)sV;
    for (int i = threadIdx.x; i < 455; i += 128) {
        float t = pr[i] + pr[1152 + i] + pr[2304 + i] + pr[3456 + i];
        if (i < 448) atomicAdd(&g_numer[b * 448 + i], t);
        else atomicAdd(&g_denom[b * SS + (i - 448)], t);
    }
}

// ---------------- kernel 5: updates -> GRU -> MLP -> slots -> q(next) ----------
// grid: 448 blocks x 128 threads; t-loops split across half-threadsets.
__global__ __launch_bounds__(128) void update_kernel(
    const float* __restrict__ bih, const float* __restrict__ bhh,
    const float* __restrict__ w1,  const float* __restrict__ b1v,
    const float* __restrict__ w2,  const float* __restrict__ b2v,
    const float* __restrict__ lg,  const float* __restrict__ lb,
    const float* __restrict__ Wq,  float* __restrict__ out)
{
    const int bs = blockIdx.x;
    const int tid = threadIdx.x;
    const int d = tid & 63, hf = tid >> 6;

    __shared__ float su[64], sh[64], shn[64], so[64], smm[128];
    __shared__ float sp[6][128];
    __shared__ float red[4];

    if (hf == 0) {
        float den = g_denom[bs];
        su[d] = g_numer[bs * 64 + d] / den;
        sh[d] = g_slots[bs * 64 + d];
    }
    __syncthreads();

    float a0 = 0.f, a1 = 0.f, a2 = 0.f, c0 = 0.f, c1 = 0.f, c2 = 0.f;
    const int tbase = hf * 32;
#pragma unroll 8
    for (int i = 0; i < 32; i++) {
        int t = tbase + i;
        float ut = su[t], ht = sh[t];
        const float* wi = &g_wihT[t * 192];
        const float* wh = &g_whhT[t * 192];
        a0 += ut * wi[d]; a1 += ut * wi[64 + d]; a2 += ut * wi[128 + d];
        c0 += ht * wh[d]; c1 += ht * wh[64 + d]; c2 += ht * wh[128 + d];
    }
    sp[0][tid] = a0; sp[1][tid] = a1; sp[2][tid] = a2;
    sp[3][tid] = c0; sp[4][tid] = c1; sp[5][tid] = c2;
    __syncthreads();

    if (hf == 0) {
        float A0 = bih[d]       + sp[0][d] + sp[0][64 + d];
        float A1 = bih[64 + d]  + sp[1][d] + sp[1][64 + d];
        float A2 = bih[128 + d] + sp[2][d] + sp[2][64 + d];
        float C0 = bhh[d]       + sp[3][d] + sp[3][64 + d];
        float C1 = bhh[64 + d]  + sp[4][d] + sp[4][64 + d];
        float C2 = bhh[128 + d] + sp[5][d] + sp[5][64 + d];
        float r = 1.f / (1.f + __expf(-(A0 + C0)));
        float z = 1.f / (1.f + __expf(-(A1 + C1)));
        float n = tanhf(A2 + r * C2);
        shn[d] = (1.f - z) * n + z * sh[d];
    }
    __syncthreads();

    float m = b1v[tid];
#pragma unroll 8
    for (int t = 0; t < 64; t++) m += shn[t] * w1[t * 128 + tid];
    smm[tid] = fmaxf(m, 0.f);
    __syncthreads();

    float op = 0.f;
#pragma unroll 8
    for (int i = 0; i < 64; i++) {
        int cc = hf * 64 + i;
        op += smm[cc] * w2[cc * 64 + d];
    }
    sp[0][tid] = op;
    __syncthreads();

    if (hf == 0) {
        float oo = shn[d] + b2v[d] + sp[0][d] + sp[0][64 + d];
        g_slots[bs * 64 + d] = oo;
        if (out) out[bs * 64 + d] = oo;
        so[d] = oo;
    }
    __syncthreads();

    if (hf == 0) {
        float v = so[d];
        float s1 = v, s2 = v * v;
#pragma unroll
        for (int o = 16; o; o >>= 1) {
            s1 += __shfl_xor_sync(0xffffffffu, s1, o);
            s2 += __shfl_xor_sync(0xffffffffu, s2, o);
        }
        if ((d & 31) == 0) { red[d >> 5] = s1; red[2 + (d >> 5)] = s2; }
    }
    __syncthreads();
    if (hf == 0) {
        float S = red[0] + red[1], S2 = red[2] + red[3];
        float mm = S * 0.015625f;
        float var = fmaxf(S2 * 0.015625f - mm * mm, 0.f);
        float inv = rsqrtf(var + 1e-5f);
        shn[d] = (so[d] - mm) * inv * lg[d] + lb[d];
    }
    __syncthreads();

    float qp = 0.f;
#pragma unroll 8
    for (int i = 0; i < 32; i++) {
        int j = hf * 32 + i;
        qp += shn[j] * Wq[j * 64 + d];
    }
    sp[0][tid] = qp;
    __syncthreads();

    if (hf == 0) {
        g_q[bs * 64 + d] = (sp[0][d] + sp[0][64 + d]) * 0.125f;
        g_numer[bs * 64 + d] = 0.f;
        if (d == 0) g_denom[bs] = 0.f;
    }
}

// ---------------- launch ----------------
extern "C" void kernel_launch(void* const* d_in, const int* in_sizes, int n_in,
                              void* d_out, int out_size) {
    (void)in_sizes; (void)n_in; (void)out_size;
    const float* x          = (const float*)d_in[0];
    const float* ln_inp_g   = (const float*)d_in[1];
    const float* ln_inp_b   = (const float*)d_in[2];
    const float* ln_slot_g  = (const float*)d_in[3];
    const float* ln_slot_b  = (const float*)d_in[4];
    const float* slots_init = (const float*)d_in[5];
    const float* Wk         = (const float*)d_in[6];
    const float* Wv         = (const float*)d_in[7];
    const float* Wq         = (const float*)d_in[8];
    const float* gwih       = (const float*)d_in[9];
    const float* gwhh       = (const float*)d_in[10];
    const float* gbih       = (const float*)d_in[11];
    const float* gbhh       = (const float*)d_in[12];
    const float* w1         = (const float*)d_in[13];
    const float* b1         = (const float*)d_in[14];
    const float* w2         = (const float*)d_in[15];
    const float* b2         = (const float*)d_in[16];
    float* out = (float*)d_out;

    // 8 launches; 4th (profiled) = update_kernel #1.
    init_kernel<<<BB * SS, 64>>>(slots_init, ln_slot_g, ln_slot_b, Wq,
                                 Wk, Wv, gwih, gwhh);                   // 1
    proj_kernel<<<(BB * NN) / 128, 256>>>(x, ln_inp_g, ln_inp_b);       // 2
    for (int it = 0; it < 3; it++) {
        attn_kernel<<<dim3(16, BB), 128>>>();                           // 3,5,7
        update_kernel<<<BB * SS, 128>>>(gbih, gbhh, w1, b1, w2, b2,
                                        ln_slot_g, ln_slot_b, Wq,
                                        it == 2 ? out : nullptr);       // 4,6,8
    }
}

// round 15
// speedup vs baseline: 2.3185x; 1.2873x over previous
#include <cuda_runtime.h>
#include <cstdint>

#define BB 64
#define NN 4096
#define SS 7

// ---------------- scratch (static device globals; no allocation) ----------------
__device__ unsigned g_k[BB * NN * 32];       // f16x2 words: 32 MB
__device__ unsigned g_v[BB * NN * 32];       // 32 MB
__device__ float g_q[BB * 448];              // q [b][s][64] (scaled by 1/8)
__device__ float g_slots[BB * SS * 64];
__device__ float g_numer[BB * 448];
__device__ float g_denom[BB * SS];
__device__ unsigned g_Bt[128 * 32];          // B^T: [n][k] f16x2 words (Wk|Wv)
__device__ float g_wihT[64 * 192];           // GRU weights transposed [t][j]
__device__ float g_whhT[64 * 192];

// ---------------- helpers ----------------
__device__ __forceinline__ unsigned h2(float lo, float hi) {
    unsigned r;
    asm("cvt.rn.f16x2.f32 %0, %1, %2;" : "=r"(r) : "f"(hi), "f"(lo));
    return r;
}
__device__ __forceinline__ uint32_t smem_u32(const void* p) {
    uint32_t a;
    asm("{ .reg .u64 t; cvta.to.shared.u64 t, %1; cvt.u32.u64 %0, t; }" : "=r"(a) : "l"(p));
    return a;
}
__device__ __forceinline__ void mma_f16(float& c0, float& c1, float& c2, float& c3,
                                        unsigned a0, unsigned a1, unsigned a2, unsigned a3,
                                        unsigned b0, unsigned b1) {
    asm volatile(
        "mma.sync.aligned.m16n8k16.row.col.f32.f16.f16.f32 "
        "{%0,%1,%2,%3}, {%4,%5,%6,%7}, {%8,%9}, {%0,%1,%2,%3};"
        : "+f"(c0), "+f"(c1), "+f"(c2), "+f"(c3)
        : "r"(a0), "r"(a1), "r"(a2), "r"(a3), "r"(b0), "r"(b1));
}
#define LDSM4(r0, r1, r2, r3, a) \
    asm volatile("ldmatrix.sync.aligned.m8n8.x4.shared.b16 {%0,%1,%2,%3}, [%4];" \
        : "=r"(r0), "=r"(r1), "=r"(r2), "=r"(r3) : "r"(a))
#define LDSM4T(r0, r1, r2, r3, a) \
    asm volatile("ldmatrix.sync.aligned.m8n8.x4.trans.shared.b16 {%0,%1,%2,%3}, [%4];" \
        : "=r"(r0), "=r"(r1), "=r"(r2), "=r"(r3) : "r"(a))
#define CP16(dst, src) \
    asm volatile("cp.async.ca.shared.global [%0], [%1], 16;" :: "r"(dst), "l"(src))
#define CP_COMMIT() asm volatile("cp.async.commit_group;" ::: "memory")
#define CP_WAIT(n)  asm volatile("cp.async.wait_group %0;" :: "n"(n) : "memory")

// ---------------- common: LN(v over 64) with 2-warp block ----------------------
__device__ __forceinline__ float block_ln64(float v, int d, float* red) {
    float s1 = v, s2 = v * v;
#pragma unroll
    for (int o = 16; o; o >>= 1) {
        s1 += __shfl_xor_sync(0xffffffffu, s1, o);
        s2 += __shfl_xor_sync(0xffffffffu, s2, o);
    }
    const int wd = d >> 5;
    if ((d & 31) == 0) { red[wd] = s1; red[2 + wd] = s2; }
    __syncthreads();
    float S = red[0] + red[1], S2 = red[2] + red[3];
    float m = S * 0.015625f;
    float var = fmaxf(S2 * 0.015625f - m * m, 0.f);
    float inv = rsqrtf(var + 1e-5f);
    return (v - m) * inv;
}

// ---------------- kernel 0: init slots/q0/zero + ALL weight prep ----------------
// grid: 448 blocks x 64 threads; gi = bs*64+d covers exactly [0, 28672).
__global__ __launch_bounds__(64) void init_kernel(
    const float* __restrict__ s0,
    const float* __restrict__ lg, const float* __restrict__ lb,
    const float* __restrict__ Wq,
    const float* __restrict__ Wk, const float* __restrict__ Wv,
    const float* __restrict__ wih, const float* __restrict__ whh)
{
    const int bs = blockIdx.x;
    const int s = bs % SS;
    const int d = threadIdx.x;
    __shared__ float ssn[64];
    __shared__ float red[4];

    const int gi = bs * 64 + d;
    if (gi < 4096) {
        int n = gi >> 5, w = gi & 31;
        const float* W = (n < 64) ? Wk : Wv;
        int nc = n & 63;
        g_Bt[gi] = h2(W[(2 * w) * 64 + nc], W[(2 * w + 1) * 64 + nc]);
    } else if (gi < 16384) {
        int m = gi - 4096;
        int t = m / 192, j = m % 192;
        g_wihT[m] = wih[j * 64 + t];
    } else {
        int m = gi - 16384;
        int t = m / 192, j = m % 192;
        g_whhT[m] = whh[j * 64 + t];
    }

    float v = s0[s * 64 + d];
    g_slots[bs * 64 + d] = v;

    float sn = block_ln64(v, d, red) * lg[d] + lb[d];
    ssn[d] = sn;
    __syncthreads();

    float q = 0.f;
#pragma unroll 8
    for (int j = 0; j < 64; j++) q += ssn[j] * Wq[j * 64 + d];
    g_q[bs * 64 + d] = q * 0.125f;
    g_numer[bs * 64 + d] = 0.f;
    if (d == 0) g_denom[bs] = 0.f;
}

// ---------------- kernel 1: fused LN + f16 HMMA GEMM -> k|v ---------------------
#define PITCH 36
__global__ __launch_bounds__(256) void proj_kernel(
    const float* __restrict__ x,
    const float* __restrict__ lg, const float* __restrict__ lb)
{
    __shared__ __align__(16) unsigned sA[128 * PITCH];
    __shared__ __align__(16) unsigned sB[128 * PITCH];

    const int tid = threadIdx.x;
    const int w = tid >> 5, lane = tid & 31;
    const int row0 = blockIdx.x * 128;

    const uint32_t sBb = smem_u32(sB);
    {
#pragma unroll
        for (int t = 0; t < 4; t++) {
            int q4 = t * 256 + tid;
            int n = q4 >> 3, m = q4 & 7;
            CP16(sBb + (n * PITCH + m * 4) * 4, (const uint4*)g_Bt + q4);
        }
        CP_COMMIT();
    }

    const float4* x4 = (const float4*)(x + (size_t)row0 * 64);
    float4 f[8];
#pragma unroll
    for (int t = 0; t < 8; t++) f[t] = x4[t * 256 + tid];

    {
        const int j = tid & 15;
        const float4 gg = ((const float4*)lg)[j];
        const float4 bb = ((const float4*)lb)[j];
#pragma unroll
        for (int t = 0; t < 8; t++) {
            float4 v = f[t];
            float s1 = v.x + v.y + v.z + v.w;
            float s2 = v.x * v.x + v.y * v.y + v.z * v.z + v.w * v.w;
#pragma unroll
            for (int o = 1; o <= 8; o <<= 1) {
                s1 += __shfl_xor_sync(0xffffffffu, s1, o);
                s2 += __shfl_xor_sync(0xffffffffu, s2, o);
            }
            float m = s1 * 0.015625f;
            float var = fmaxf(s2 * 0.015625f - m * m, 0.f);
            float inv = rsqrtf(var + 1e-5f);
            float y0 = (v.x - m) * inv * gg.x + bb.x;
            float y1 = (v.y - m) * inv * gg.y + bb.y;
            float y2 = (v.z - m) * inv * gg.z + bb.z;
            float y3 = (v.w - m) * inv * gg.w + bb.w;
            int row = t * 16 + (tid >> 4);
            *(uint2*)&sA[row * PITCH + j * 2] = make_uint2(h2(y0, y1), h2(y2, y3));
        }
    }
    CP_WAIT(0);
    __syncthreads();

    const int r0 = w * 16;
    const int qr = lane >> 2, qc = lane & 3;
    const int ra = r0 + qr, rb = ra + 8;

    unsigned afr[4][4];
    {
        const uint32_t aA = smem_u32(sA) +
            (((r0 + ((lane >> 3) & 1) * 8 + (lane & 7)) * PITCH + (lane >> 4) * 4) << 2);
#pragma unroll
        for (int ks = 0; ks < 4; ks++)
            LDSM4(afr[ks][0], afr[ks][1], afr[ks][2], afr[ks][3], aA + (ks * 8 << 2));
    }
    __syncthreads();

    const uint32_t bB = sBb + ((((lane & 7)) * PITCH + ((lane >> 3) & 1) * 4 + (lane >> 4) * 8) << 2);

#pragma unroll
    for (int pass = 0; pass < 2; pass++) {
#pragma unroll
        for (int b8 = 0; b8 < 8; b8++) {
            float c0 = 0.f, c1 = 0.f, c2 = 0.f, c3 = 0.f;
            const uint32_t a0 = bB + (((pass * 8 + b8) * 8 * PITCH) << 2);
            unsigned q0, q1, q2, q3;
            LDSM4(q0, q1, q2, q3, a0);
            mma_f16(c0, c1, c2, c3, afr[0][0], afr[0][1], afr[0][2], afr[0][3], q0, q1);
            mma_f16(c0, c1, c2, c3, afr[1][0], afr[1][1], afr[1][2], afr[1][3], q2, q3);
            LDSM4(q0, q1, q2, q3, a0 + 64);
            mma_f16(c0, c1, c2, c3, afr[2][0], afr[2][1], afr[2][2], afr[2][3], q0, q1);
            mma_f16(c0, c1, c2, c3, afr[3][0], afr[3][1], afr[3][2], afr[3][3], q2, q3);
            sA[ra * PITCH + b8 * 4 + qc] = h2(c0, c1);
            sA[rb * PITCH + b8 * 4 + qc] = h2(c2, c3);
        }
        __syncthreads();
        unsigned* dst = pass ? g_v : g_k;
#pragma unroll
        for (int p = 0; p < 4; p++) {
            int row = p * 32 + (tid >> 3);
            uint4 val = *(uint4*)&sA[row * PITCH + (tid & 7) * 4];
            *(uint4*)&dst[(size_t)(row0 + row) * 32 + (tid & 7) * 4] = val;
        }
        __syncthreads();
    }
}

// ---------------- attn helpers ----------------
__device__ __forceinline__ void stage_cp(uint32_t base, const uint4* g, int l) {
    const uint32_t off = (((l >> 3)) * 36 + (l & 7) * 4) << 2;
#pragma unroll
    for (int i = 0; i < 8; i++)
        CP16(base + off + i * 576, g + i * 32 + l);
    CP_COMMIT();
}
__device__ __forceinline__ void ldsm_tiles(unsigned t[4][8], uint32_t base, int l, bool trans) {
#pragma unroll
    for (int g = 0; g < 4; g++)
#pragma unroll
        for (int cc = 0; cc < 2; cc++) {
            uint32_t a = base + (((8 * g + (l & 7)) * 36 + (4 * cc + (l >> 3)) * 4) << 2);
            if (trans) LDSM4T(t[g][4 * cc], t[g][4 * cc + 1], t[g][4 * cc + 2], t[g][4 * cc + 3], a);
            else       LDSM4 (t[g][4 * cc], t[g][4 * cc + 1], t[g][4 * cc + 2], t[g][4 * cc + 3], a);
        }
}
__device__ __forceinline__ float softmax_chunk(unsigned tiles[4][8], unsigned aq[4][2],
                                               float wreg[4][2], int s) {
    float dum0 = 0.f, dum1 = 0.f;
    float cl[4][2];
#pragma unroll
    for (int g = 0; g < 4; g++) {
        cl[g][0] = 0.f; cl[g][1] = 0.f;
#pragma unroll
        for (int ks = 0; ks < 4; ks++)
            mma_f16(cl[g][0], cl[g][1], dum0, dum1,
                    aq[ks][0], 0u, aq[ks][1], 0u, tiles[g][2 * ks], tiles[g][2 * ks + 1]);
    }
    float dl = 0.f;
#pragma unroll
    for (int g = 0; g < 4; g++) {
        float x0 = (s < 7) ? cl[g][0] : -1e30f;
        float x1 = (s < 7) ? cl[g][1] : -1e30f;
        float m0 = x0, m1 = x1;
#pragma unroll
        for (int o = 4; o <= 16; o <<= 1) {
            m0 = fmaxf(m0, __shfl_xor_sync(0xffffffffu, m0, o));
            m1 = fmaxf(m1, __shfl_xor_sync(0xffffffffu, m1, o));
        }
        float e0 = __expf(x0 - m0), e1 = __expf(x1 - m1);
        float t0 = e0, t1 = e1;
#pragma unroll
        for (int o = 4; o <= 16; o <<= 1) {
            t0 += __shfl_xor_sync(0xffffffffu, t0, o);
            t1 += __shfl_xor_sync(0xffffffffu, t1, o);
        }
        float w0 = (s < 7) ? e0 / t0 + 1e-8f : 0.f;
        float w1 = (s < 7) ? e1 / t1 + 1e-8f : 0.f;
        dl += w0 + w1;
        wreg[g][0] = w0; wreg[g][1] = w1;
    }
    return dl;
}
__device__ __forceinline__ void phase2_chunk(unsigned tiles[4][8], float wreg[4][2],
                                             float cu[8][2]) {
    float dum0 = 0.f, dum1 = 0.f;
    unsigned aw[2][2];
    aw[0][0] = h2(wreg[0][0], wreg[0][1]);
    aw[0][1] = h2(wreg[1][0], wreg[1][1]);
    aw[1][0] = h2(wreg[2][0], wreg[2][1]);
    aw[1][1] = h2(wreg[3][0], wreg[3][1]);
#pragma unroll
    for (int t = 0; t < 8; t++) {
#pragma unroll
        for (int ks = 0; ks < 2; ks++)
            mma_f16(cu[t][0], cu[t][1], dum0, dum1,
                    aw[ks][0], 0u, aw[ks][1], 0u, tiles[2 * ks][t], tiles[2 * ks + 1][t]);
    }
}

// ---------------- kernel 4: attention (64 rows/warp, cp.async pipeline) ---------
__global__ __launch_bounds__(128, 5) void attn_kernel() {
    const int b = blockIdx.y;
    const int w = threadIdx.x >> 5, l = threadIdx.x & 31;
    const int s = l >> 2, c = l & 3;

    __shared__ __align__(16) unsigned sK[4 * 1152];
    __shared__ __align__(16) unsigned sV[4 * 1152];
    unsigned* sk = sK + w * 1152;
    unsigned* sv = sV + w * 1152;
    const uint32_t skb = smem_u32(sk);
    const uint32_t svb = smem_u32(sv);

    unsigned aq[4][2];
    {
        const float* qb = g_q + b * 448 + s * 64;
#pragma unroll
        for (int ks = 0; ks < 4; ks++) {
            if (s < 7) {
                float2 f0 = *(const float2*)&qb[ks * 16 + 2 * c];
                float2 f1 = *(const float2*)&qb[ks * 16 + 8 + 2 * c];
                aq[ks][0] = h2(f0.x, f0.y);
                aq[ks][1] = h2(f1.x, f1.y);
            } else { aq[ks][0] = 0u; aq[ks][1] = 0u; }
        }
    }

    const size_t rowbase = (size_t)b * NN + blockIdx.x * 256 + w * 64;
    const uint4* kg = (const uint4*)(g_k + rowbase * 32);
    const uint4* vg = (const uint4*)(g_v + rowbase * 32);

    stage_cp(skb, kg, l);
    stage_cp(svb, vg, l);

    unsigned tiles[4][8];
    float cu[8][2];
#pragma unroll
    for (int t = 0; t < 8; t++) { cu[t][0] = 0.f; cu[t][1] = 0.f; }
    float wreg[4][2];
    float dlT = 0.f;

    CP_WAIT(1); __syncwarp();
    ldsm_tiles(tiles, skb, l, false);
    stage_cp(skb, kg + 256, l);
    dlT += softmax_chunk(tiles, aq, wreg, s);
    CP_WAIT(1); __syncwarp();
    ldsm_tiles(tiles, svb, l, true);
    stage_cp(svb, vg + 256, l);
    phase2_chunk(tiles, wreg, cu);

    CP_WAIT(1); __syncwarp();
    ldsm_tiles(tiles, skb, l, false);
    dlT += softmax_chunk(tiles, aq, wreg, s);
    CP_WAIT(0); __syncwarp();
    ldsm_tiles(tiles, svb, l, true);
    phase2_chunk(tiles, wreg, cu);

    dlT += __shfl_xor_sync(0xffffffffu, dlT, 1);
    dlT += __shfl_xor_sync(0xffffffffu, dlT, 2);
    float* red = (float*)sv;
    if (s < 7) {
#pragma unroll
        for (int t = 0; t < 8; t++)
            *(float2*)&red[s * 64 + 8 * t + 2 * c] = make_float2(cu[t][0], cu[t][1]);
        if (c == 0) red[448 + s] = dlT;
    }
    __syncthreads();

    float* pr = (float*)sV;
    for (int i = threadIdx.x; i < 455; i += 128) {
        float t = pr[i] + pr[1152 + i] + pr[2304 + i] + pr[3456 + i];
        if (i < 448) atomicAdd(&g_numer[b * 448 + i], t);
        else atomicAdd(&g_denom[b * SS + (i - 448)], t);
    }
}

// ---------------- kernel 5: updates -> GRU -> MLP -> slots -> q(next) ----------
// grid: 448 blocks x 256 threads; all GEMV stages split 4 ways (latency hiding).
__global__ __launch_bounds__(256) void update_kernel(
    const float* __restrict__ bih, const float* __restrict__ bhh,
    const float* __restrict__ w1,  const float* __restrict__ b1v,
    const float* __restrict__ w2,  const float* __restrict__ b2v,
    const float* __restrict__ lg,  const float* __restrict__ lb,
    const float* __restrict__ Wq,  float* __restrict__ out)
{
    const int bs = blockIdx.x;
    const int tid = threadIdx.x;
    const int d = tid & 63, qf = tid >> 6;     // quarter 0..3

    __shared__ float su[64], sh[64], shn[64], so[64], smm[128];
    __shared__ float sp[6][256];
    __shared__ float red[4];

    if (qf == 0) {
        float den = g_denom[bs];
        su[d] = g_numer[bs * 64 + d] / den;
        sh[d] = g_slots[bs * 64 + d];
    }
    __syncthreads();

    // GRU partials: quarter qf handles t in [qf*16, qf*16+16)
    float a0 = 0.f, a1 = 0.f, a2 = 0.f, c0 = 0.f, c1 = 0.f, c2 = 0.f;
    const int tbase = qf * 16;
#pragma unroll 8
    for (int i = 0; i < 16; i++) {
        int t = tbase + i;
        float ut = su[t], ht = sh[t];
        const float* wi = &g_wihT[t * 192];
        const float* wh = &g_whhT[t * 192];
        a0 += ut * wi[d]; a1 += ut * wi[64 + d]; a2 += ut * wi[128 + d];
        c0 += ht * wh[d]; c1 += ht * wh[64 + d]; c2 += ht * wh[128 + d];
    }
    sp[0][tid] = a0; sp[1][tid] = a1; sp[2][tid] = a2;
    sp[3][tid] = c0; sp[4][tid] = c1; sp[5][tid] = c2;
    __syncthreads();

    if (qf == 0) {
        float A0 = bih[d]       + sp[0][d] + sp[0][64 + d] + sp[0][128 + d] + sp[0][192 + d];
        float A1 = bih[64 + d]  + sp[1][d] + sp[1][64 + d] + sp[1][128 + d] + sp[1][192 + d];
        float A2 = bih[128 + d] + sp[2][d] + sp[2][64 + d] + sp[2][128 + d] + sp[2][192 + d];
        float C0 = bhh[d]       + sp[3][d] + sp[3][64 + d] + sp[3][128 + d] + sp[3][192 + d];
        float C1 = bhh[64 + d]  + sp[4][d] + sp[4][64 + d] + sp[4][128 + d] + sp[4][192 + d];
        float C2 = bhh[128 + d] + sp[5][d] + sp[5][64 + d] + sp[5][128 + d] + sp[5][192 + d];
        float r = 1.f / (1.f + __expf(-(A0 + C0)));
        float z = 1.f / (1.f + __expf(-(A1 + C1)));
        float n = tanhf(A2 + r * C2);
        shn[d] = (1.f - z) * n + z * sh[d];
    }
    __syncthreads();

    // MLP1: channel j = tid&127, half = tid>>7 covers 32 t each
    {
        const int j = tid & 127, half = tid >> 7;
        float m = half ? 0.f : b1v[j];
#pragma unroll 8
        for (int i = 0; i < 32; i++) {
            int t = half * 32 + i;
            m += shn[t] * w1[t * 128 + j];
        }
        sp[0][tid] = m;
    }
    __syncthreads();
    if (tid < 128) smm[tid] = fmaxf(sp[0][tid] + sp[0][128 + tid], 0.f);
    __syncthreads();

    // MLP2: quarter qf handles cc in [qf*32, qf*32+32)
    {
        float op = 0.f;
#pragma unroll 8
        for (int i = 0; i < 32; i++) {
            int cc = qf * 32 + i;
            op += smm[cc] * w2[cc * 64 + d];
        }
        sp[0][tid] = op;
    }
    __syncthreads();

    if (qf == 0) {
        float oo = shn[d] + b2v[d] + sp[0][d] + sp[0][64 + d] + sp[0][128 + d] + sp[0][192 + d];
        g_slots[bs * 64 + d] = oo;
        if (out) out[bs * 64 + d] = oo;
        so[d] = oo;
    }
    __syncthreads();

    // LN on new slots (first 2 warps)
    if (qf == 0) {
        float v = so[d];
        float s1 = v, s2 = v * v;
#pragma unroll
        for (int o = 16; o; o >>= 1) {
            s1 += __shfl_xor_sync(0xffffffffu, s1, o);
            s2 += __shfl_xor_sync(0xffffffffu, s2, o);
        }
        if ((d & 31) == 0) { red[d >> 5] = s1; red[2 + (d >> 5)] = s2; }
    }
    __syncthreads();
    if (qf == 0) {
        float S = red[0] + red[1], S2 = red[2] + red[3];
        float mm = S * 0.015625f;
        float var = fmaxf(S2 * 0.015625f - mm * mm, 0.f);
        float inv = rsqrtf(var + 1e-5f);
        shn[d] = (so[d] - mm) * inv * lg[d] + lb[d];
    }
    __syncthreads();

    // q projection: quarter qf handles j in [qf*16, qf*16+16)
    {
        float qp = 0.f;
#pragma unroll 8
        for (int i = 0; i < 16; i++) {
            int j = qf * 16 + i;
            qp += shn[j] * Wq[j * 64 + d];
        }
        sp[0][tid] = qp;
    }
    __syncthreads();

    if (qf == 0) {
        g_q[bs * 64 + d] = (sp[0][d] + sp[0][64 + d] + sp[0][128 + d] + sp[0][192 + d]) * 0.125f;
        g_numer[bs * 64 + d] = 0.f;
        if (d == 0) g_denom[bs] = 0.f;
    }
}

// ---------------- launch ----------------
extern "C" void kernel_launch(void* const* d_in, const int* in_sizes, int n_in,
                              void* d_out, int out_size) {
    (void)in_sizes; (void)n_in; (void)out_size;
    const float* x          = (const float*)d_in[0];
    const float* ln_inp_g   = (const float*)d_in[1];
    const float* ln_inp_b   = (const float*)d_in[2];
    const float* ln_slot_g  = (const float*)d_in[3];
    const float* ln_slot_b   = (const float*)d_in[4];
    const float* slots_init = (const float*)d_in[5];
    const float* Wk         = (const float*)d_in[6];
    const float* Wv         = (const float*)d_in[7];
    const float* Wq         = (const float*)d_in[8];
    const float* gwih       = (const float*)d_in[9];
    const float* gwhh       = (const float*)d_in[10];
    const float* gbih       = (const float*)d_in[11];
    const float* gbhh       = (const float*)d_in[12];
    const float* w1         = (const float*)d_in[13];
    const float* b1         = (const float*)d_in[14];
    const float* w2         = (const float*)d_in[15];
    const float* b2         = (const float*)d_in[16];
    float* out = (float*)d_out;

    // 8 launches; 4th (profiled) = update_kernel #1 (the changed kernel).
    init_kernel<<<BB * SS, 64>>>(slots_init, ln_slot_g, ln_slot_b, Wq,
                                 Wk, Wv, gwih, gwhh);                   // 1
    proj_kernel<<<(BB * NN) / 128, 256>>>(x, ln_inp_g, ln_inp_b);       // 2
    for (int it = 0; it < 3; it++) {
        attn_kernel<<<dim3(16, BB), 128>>>();                           // 3,5,7
        update_kernel<<<BB * SS, 256>>>(gbih, gbhh, w1, b1, w2, b2,
                                        ln_slot_g, ln_slot_b, Wq,
                                        it == 2 ? out : nullptr);       // 4,6,8
    }
}

// round 16
// speedup vs baseline: 2.8574x; 1.2324x over previous
#include <cuda_runtime.h>
#include <cstdint>

#define BB 64
#define NN 4096
#define SS 7

// ---------------- scratch (static device globals; no allocation) ----------------
__device__ unsigned g_k[BB * NN * 32];       // f16x2 words: 32 MB
__device__ unsigned g_v[BB * NN * 32];       // 32 MB
__device__ float g_q[BB * 448];              // q [b][s][64] (scaled by 1/8)
__device__ float g_slots[BB * SS * 64];
__device__ float g_numer[BB * 448];
__device__ float g_denom[BB * SS];
__device__ unsigned g_Bt[128 * 32];          // B^T: [n][k] f16x2 words (Wk|Wv)
__device__ float g_wihT[64 * 192];           // GRU weights transposed [t][j]
__device__ float g_whhT[64 * 192];

// ---------------- helpers ----------------
__device__ __forceinline__ unsigned h2(float lo, float hi) {
    unsigned r;
    asm("cvt.rn.f16x2.f32 %0, %1, %2;" : "=r"(r) : "f"(hi), "f"(lo));
    return r;
}
__device__ __forceinline__ uint32_t smem_u32(const void* p) {
    uint32_t a;
    asm("{ .reg .u64 t; cvta.to.shared.u64 t, %1; cvt.u32.u64 %0, t; }" : "=r"(a) : "l"(p));
    return a;
}
__device__ __forceinline__ void mma_f16(float& c0, float& c1, float& c2, float& c3,
                                        unsigned a0, unsigned a1, unsigned a2, unsigned a3,
                                        unsigned b0, unsigned b1) {
    asm volatile(
        "mma.sync.aligned.m16n8k16.row.col.f32.f16.f16.f32 "
        "{%0,%1,%2,%3}, {%4,%5,%6,%7}, {%8,%9}, {%0,%1,%2,%3};"
        : "+f"(c0), "+f"(c1), "+f"(c2), "+f"(c3)
        : "r"(a0), "r"(a1), "r"(a2), "r"(a3), "r"(b0), "r"(b1));
}
#define LDSM4(r0, r1, r2, r3, a) \
    asm volatile("ldmatrix.sync.aligned.m8n8.x4.shared.b16 {%0,%1,%2,%3}, [%4];" \
        : "=r"(r0), "=r"(r1), "=r"(r2), "=r"(r3) : "r"(a))
#define LDSM4T(r0, r1, r2, r3, a) \
    asm volatile("ldmatrix.sync.aligned.m8n8.x4.trans.shared.b16 {%0,%1,%2,%3}, [%4];" \
        : "=r"(r0), "=r"(r1), "=r"(r2), "=r"(r3) : "r"(a))
#define CP16(dst, src) \
    asm volatile("cp.async.ca.shared.global [%0], [%1], 16;" :: "r"(dst), "l"(src))
#define CP16H(dst, src, pol) \
    asm volatile("cp.async.ca.shared.global.L2::cache_hint [%0], [%1], 16, %2;" \
        :: "r"(dst), "l"(src), "l"(pol))
#define CP_COMMIT() asm volatile("cp.async.commit_group;" ::: "memory")
#define CP_WAIT(n)  asm volatile("cp.async.wait_group %0;" :: "n"(n) : "memory")

__device__ __forceinline__ unsigned long long pol_evict_last() {
    unsigned long long p;
    asm("createpolicy.fractional.L2::evict_last.b64 %0, 1.0;" : "=l"(p));
    return p;
}
__device__ __forceinline__ unsigned long long pol_evict_first() {
    unsigned long long p;
    asm("createpolicy.fractional.L2::evict_first.b64 %0, 1.0;" : "=l"(p));
    return p;
}

// ---------------- common: LN(v over 64) with 2-warp block ----------------------
__device__ __forceinline__ float block_ln64(float v, int d, float* red) {
    float s1 = v, s2 = v * v;
#pragma unroll
    for (int o = 16; o; o >>= 1) {
        s1 += __shfl_xor_sync(0xffffffffu, s1, o);
        s2 += __shfl_xor_sync(0xffffffffu, s2, o);
    }
    const int wd = d >> 5;
    if ((d & 31) == 0) { red[wd] = s1; red[2 + wd] = s2; }
    __syncthreads();
    float S = red[0] + red[1], S2 = red[2] + red[3];
    float m = S * 0.015625f;
    float var = fmaxf(S2 * 0.015625f - m * m, 0.f);
    float inv = rsqrtf(var + 1e-5f);
    return (v - m) * inv;
}

// ---------------- kernel 0: init slots/q0/zero + ALL weight prep ----------------
__global__ __launch_bounds__(64) void init_kernel(
    const float* __restrict__ s0,
    const float* __restrict__ lg, const float* __restrict__ lb,
    const float* __restrict__ Wq,
    const float* __restrict__ Wk, const float* __restrict__ Wv,
    const float* __restrict__ wih, const float* __restrict__ whh)
{
    const int bs = blockIdx.x;
    const int s = bs % SS;
    const int d = threadIdx.x;
    __shared__ float ssn[64];
    __shared__ float red[4];

    const int gi = bs * 64 + d;
    if (gi < 4096) {
        int n = gi >> 5, w = gi & 31;
        const float* W = (n < 64) ? Wk : Wv;
        int nc = n & 63;
        g_Bt[gi] = h2(W[(2 * w) * 64 + nc], W[(2 * w + 1) * 64 + nc]);
    } else if (gi < 16384) {
        int m = gi - 4096;
        int t = m / 192, j = m % 192;
        g_wihT[m] = wih[j * 64 + t];
    } else {
        int m = gi - 16384;
        int t = m / 192, j = m % 192;
        g_whhT[m] = whh[j * 64 + t];
    }

    float v = s0[s * 64 + d];
    g_slots[bs * 64 + d] = v;

    float sn = block_ln64(v, d, red) * lg[d] + lb[d];
    ssn[d] = sn;
    __syncthreads();

    float q = 0.f;
#pragma unroll 8
    for (int j = 0; j < 64; j++) q += ssn[j] * Wq[j * 64 + d];
    g_q[bs * 64 + d] = q * 0.125f;
    g_numer[bs * 64 + d] = 0.f;
    if (d == 0) g_denom[bs] = 0.f;
}

// ---------------- kernel 1: fused LN + f16 HMMA GEMM -> k|v ---------------------
#define PITCH 36
__global__ __launch_bounds__(256) void proj_kernel(
    const float* __restrict__ x,
    const float* __restrict__ lg, const float* __restrict__ lb)
{
    __shared__ __align__(16) unsigned sA[128 * PITCH];
    __shared__ __align__(16) unsigned sB[128 * PITCH];

    const int tid = threadIdx.x;
    const int w = tid >> 5, lane = tid & 31;
    const int row0 = blockIdx.x * 128;
    const unsigned long long polEF = pol_evict_first();
    const unsigned long long polEL = pol_evict_last();

    const uint32_t sBb = smem_u32(sB);
    {
#pragma unroll
        for (int t = 0; t < 4; t++) {
            int q4 = t * 256 + tid;
            int n = q4 >> 3, m = q4 & 7;
            CP16(sBb + (n * PITCH + m * 4) * 4, (const uint4*)g_Bt + q4);
        }
        CP_COMMIT();
    }

    // x read with evict_first: don't let the streaming input evict k/v in L2
    const float4* x4 = (const float4*)(x + (size_t)row0 * 64);
    float4 f[8];
#pragma unroll
    for (int t = 0; t < 8; t++) {
        asm("ld.global.nc.L2::cache_hint.v4.f32 {%0,%1,%2,%3}, [%4], %5;"
            : "=f"(f[t].x), "=f"(f[t].y), "=f"(f[t].z), "=f"(f[t].w)
            : "l"(x4 + t * 256 + tid), "l"(polEF));
    }

    {
        const int j = tid & 15;
        const float4 gg = ((const float4*)lg)[j];
        const float4 bb = ((const float4*)lb)[j];
#pragma unroll
        for (int t = 0; t < 8; t++) {
            float4 v = f[t];
            float s1 = v.x + v.y + v.z + v.w;
            float s2 = v.x * v.x + v.y * v.y + v.z * v.z + v.w * v.w;
#pragma unroll
            for (int o = 1; o <= 8; o <<= 1) {
                s1 += __shfl_xor_sync(0xffffffffu, s1, o);
                s2 += __shfl_xor_sync(0xffffffffu, s2, o);
            }
            float m = s1 * 0.015625f;
            float var = fmaxf(s2 * 0.015625f - m * m, 0.f);
            float inv = rsqrtf(var + 1e-5f);
            float y0 = (v.x - m) * inv * gg.x + bb.x;
            float y1 = (v.y - m) * inv * gg.y + bb.y;
            float y2 = (v.z - m) * inv * gg.z + bb.z;
            float y3 = (v.w - m) * inv * gg.w + bb.w;
            int row = t * 16 + (tid >> 4);
            *(uint2*)&sA[row * PITCH + j * 2] = make_uint2(h2(y0, y1), h2(y2, y3));
        }
    }
    CP_WAIT(0);
    __syncthreads();

    const int r0 = w * 16;
    const int qr = lane >> 2, qc = lane & 3;
    const int ra = r0 + qr, rb = ra + 8;

    unsigned afr[4][4];
    {
        const uint32_t aA = smem_u32(sA) +
            (((r0 + ((lane >> 3) & 1) * 8 + (lane & 7)) * PITCH + (lane >> 4) * 4) << 2);
#pragma unroll
        for (int ks = 0; ks < 4; ks++)
            LDSM4(afr[ks][0], afr[ks][1], afr[ks][2], afr[ks][3], aA + (ks * 8 << 2));
    }
    __syncthreads();

    const uint32_t bB = sBb + ((((lane & 7)) * PITCH + ((lane >> 3) & 1) * 4 + (lane >> 4) * 8) << 2);

#pragma unroll
    for (int pass = 0; pass < 2; pass++) {
#pragma unroll
        for (int b8 = 0; b8 < 8; b8++) {
            float c0 = 0.f, c1 = 0.f, c2 = 0.f, c3 = 0.f;
            const uint32_t a0 = bB + (((pass * 8 + b8) * 8 * PITCH) << 2);
            unsigned q0, q1, q2, q3;
            LDSM4(q0, q1, q2, q3, a0);
            mma_f16(c0, c1, c2, c3, afr[0][0], afr[0][1], afr[0][2], afr[0][3], q0, q1);
            mma_f16(c0, c1, c2, c3, afr[1][0], afr[1][1], afr[1][2], afr[1][3], q2, q3);
            LDSM4(q0, q1, q2, q3, a0 + 64);
            mma_f16(c0, c1, c2, c3, afr[2][0], afr[2][1], afr[2][2], afr[2][3], q0, q1);
            mma_f16(c0, c1, c2, c3, afr[3][0], afr[3][1], afr[3][2], afr[3][3], q2, q3);
            sA[ra * PITCH + b8 * 4 + qc] = h2(c0, c1);
            sA[rb * PITCH + b8 * 4 + qc] = h2(c2, c3);
        }
        __syncthreads();
        unsigned* dst = pass ? g_v : g_k;
#pragma unroll
        for (int p = 0; p < 4; p++) {
            int row = p * 32 + (tid >> 3);
            uint4 val = *(uint4*)&sA[row * PITCH + (tid & 7) * 4];
            // k/v stores with evict_last: keep resident for the 3 attn passes
            asm volatile("st.global.L2::cache_hint.v4.b32 [%0], {%1,%2,%3,%4}, %5;"
                :: "l"(&dst[(size_t)(row0 + row) * 32 + (tid & 7) * 4]),
                   "r"(val.x), "r"(val.y), "r"(val.z), "r"(val.w), "l"(polEL)
                : "memory");
        }
        __syncthreads();
    }
}

// ---------------- attn helpers ----------------
__device__ __forceinline__ void stage_cp(uint32_t base, const uint4* g, int l,
                                         unsigned long long pol) {
    const uint32_t off = (((l >> 3)) * 36 + (l & 7) * 4) << 2;
#pragma unroll
    for (int i = 0; i < 8; i++)
        CP16H(base + off + i * 576, g + i * 32 + l, pol);
    CP_COMMIT();
}
__device__ __forceinline__ void ldsm_tiles(unsigned t[4][8], uint32_t base, int l, bool trans) {
#pragma unroll
    for (int g = 0; g < 4; g++)
#pragma unroll
        for (int cc = 0; cc < 2; cc++) {
            uint32_t a = base + (((8 * g + (l & 7)) * 36 + (4 * cc + (l >> 3)) * 4) << 2);
            if (trans) LDSM4T(t[g][4 * cc], t[g][4 * cc + 1], t[g][4 * cc + 2], t[g][4 * cc + 3], a);
            else       LDSM4 (t[g][4 * cc], t[g][4 * cc + 1], t[g][4 * cc + 2], t[g][4 * cc + 3], a);
        }
}
__device__ __forceinline__ float softmax_chunk(unsigned tiles[4][8], unsigned aq[4][2],
                                               float wreg[4][2], int s) {
    float dum0 = 0.f, dum1 = 0.f;
    float cl[4][2];
#pragma unroll
    for (int g = 0; g < 4; g++) {
        cl[g][0] = 0.f; cl[g][1] = 0.f;
#pragma unroll
        for (int ks = 0; ks < 4; ks++)
            mma_f16(cl[g][0], cl[g][1], dum0, dum1,
                    aq[ks][0], 0u, aq[ks][1], 0u, tiles[g][2 * ks], tiles[g][2 * ks + 1]);
    }
    float dl = 0.f;
#pragma unroll
    for (int g = 0; g < 4; g++) {
        float x0 = (s < 7) ? cl[g][0] : -1e30f;
        float x1 = (s < 7) ? cl[g][1] : -1e30f;
        float m0 = x0, m1 = x1;
#pragma unroll
        for (int o = 4; o <= 16; o <<= 1) {
            m0 = fmaxf(m0, __shfl_xor_sync(0xffffffffu, m0, o));
            m1 = fmaxf(m1, __shfl_xor_sync(0xffffffffu, m1, o));
        }
        float e0 = __expf(x0 - m0), e1 = __expf(x1 - m1);
        float t0 = e0, t1 = e1;
#pragma unroll
        for (int o = 4; o <= 16; o <<= 1) {
            t0 += __shfl_xor_sync(0xffffffffu, t0, o);
            t1 += __shfl_xor_sync(0xffffffffu, t1, o);
        }
        float w0 = (s < 7) ? e0 / t0 + 1e-8f : 0.f;
        float w1 = (s < 7) ? e1 / t1 + 1e-8f : 0.f;
        dl += w0 + w1;
        wreg[g][0] = w0; wreg[g][1] = w1;
    }
    return dl;
}
__device__ __forceinline__ void phase2_chunk(unsigned tiles[4][8], float wreg[4][2],
                                             float cu[8][2]) {
    float dum0 = 0.f, dum1 = 0.f;
    unsigned aw[2][2];
    aw[0][0] = h2(wreg[0][0], wreg[0][1]);
    aw[0][1] = h2(wreg[1][0], wreg[1][1]);
    aw[1][0] = h2(wreg[2][0], wreg[2][1]);
    aw[1][1] = h2(wreg[3][0], wreg[3][1]);
#pragma unroll
    for (int t = 0; t < 8; t++) {
#pragma unroll
        for (int ks = 0; ks < 2; ks++)
            mma_f16(cu[t][0], cu[t][1], dum0, dum1,
                    aw[ks][0], 0u, aw[ks][1], 0u, tiles[2 * ks][t], tiles[2 * ks + 1][t]);
    }
}

// ---------------- kernel 4: attention (64 rows/warp, cp.async pipeline) ---------
__global__ __launch_bounds__(128, 5) void attn_kernel() {
    const int b = blockIdx.y;
    const int w = threadIdx.x >> 5, l = threadIdx.x & 31;
    const int s = l >> 2, c = l & 3;
    const unsigned long long polEL = pol_evict_last();

    __shared__ __align__(16) unsigned sK[4 * 1152];
    __shared__ __align__(16) unsigned sV[4 * 1152];
    unsigned* sk = sK + w * 1152;
    unsigned* sv = sV + w * 1152;
    const uint32_t skb = smem_u32(sk);
    const uint32_t svb = smem_u32(sv);

    unsigned aq[4][2];
    {
        const float* qb = g_q + b * 448 + s * 64;
#pragma unroll
        for (int ks = 0; ks < 4; ks++) {
            if (s < 7) {
                float2 f0 = *(const float2*)&qb[ks * 16 + 2 * c];
                float2 f1 = *(const float2*)&qb[ks * 16 + 8 + 2 * c];
                aq[ks][0] = h2(f0.x, f0.y);
                aq[ks][1] = h2(f1.x, f1.y);
            } else { aq[ks][0] = 0u; aq[ks][1] = 0u; }
        }
    }

    const size_t rowbase = (size_t)b * NN + blockIdx.x * 256 + w * 64;
    const uint4* kg = (const uint4*)(g_k + rowbase * 32);
    const uint4* vg = (const uint4*)(g_v + rowbase * 32);

    stage_cp(skb, kg, l, polEL);
    stage_cp(svb, vg, l, polEL);

    unsigned tiles[4][8];
    float cu[8][2];
#pragma unroll
    for (int t = 0; t < 8; t++) { cu[t][0] = 0.f; cu[t][1] = 0.f; }
    float wreg[4][2];
    float dlT = 0.f;

    CP_WAIT(1); __syncwarp();
    ldsm_tiles(tiles, skb, l, false);
    stage_cp(skb, kg + 256, l, polEL);
    dlT += softmax_chunk(tiles, aq, wreg, s);
    CP_WAIT(1); __syncwarp();
    ldsm_tiles(tiles, svb, l, true);
    stage_cp(svb, vg + 256, l, polEL);
    phase2_chunk(tiles, wreg, cu);

    CP_WAIT(1); __syncwarp();
    ldsm_tiles(tiles, skb, l, false);
    dlT += softmax_chunk(tiles, aq, wreg, s);
    CP_WAIT(0); __syncwarp();
    ldsm_tiles(tiles, svb, l, true);
    phase2_chunk(tiles, wreg, cu);

    dlT += __shfl_xor_sync(0xffffffffu, dlT, 1);
    dlT += __shfl_xor_sync(0xffffffffu, dlT, 2);
    float* red = (float*)sv;
    if (s < 7) {
#pragma unroll
        for (int t = 0; t < 8; t++)
            *(float2*)&red[s * 64 + 8 * t + 2 * c] = make_float2(cu[t][0], cu[t][1]);
        if (c == 0) red[448 + s] = dlT;
    }
    __syncthreads();

    float* pr = (float*)sV;
    for (int i = threadIdx.x; i < 455; i += 128) {
        float t = pr[i] + pr[1152 + i] + pr[2304 + i] + pr[3456 + i];
        if (i < 448) atomicAdd(&g_numer[b * 448 + i], t);
        else atomicAdd(&g_denom[b * SS + (i - 448)], t);
    }
}

// ---------------- kernel 5: updates -> GRU -> MLP -> slots -> q(next) ----------
// grid: 448 blocks x 512 threads; all GEMV stages split 8 ways.
__global__ __launch_bounds__(512) void update_kernel(
    const float* __restrict__ bih, const float* __restrict__ bhh,
    const float* __restrict__ w1,  const float* __restrict__ b1v,
    const float* __restrict__ w2,  const float* __restrict__ b2v,
    const float* __restrict__ lg,  const float* __restrict__ lb,
    const float* __restrict__ Wq,  float* __restrict__ out)
{
    const int bs = blockIdx.x;
    const int tid = threadIdx.x;
    const int d = tid & 63, ef = tid >> 6;     // eighth 0..7

    __shared__ float su[64], sh[64], shn[64], so[64], smm[128];
    __shared__ float sp[6][512];
    __shared__ float red[4];

    if (ef == 0) {
        float den = g_denom[bs];
        su[d] = g_numer[bs * 64 + d] / den;
        sh[d] = g_slots[bs * 64 + d];
    }
    __syncthreads();

    // GRU partials: eighth ef handles t in [ef*8, ef*8+8)
    float a0 = 0.f, a1 = 0.f, a2 = 0.f, c0 = 0.f, c1 = 0.f, c2 = 0.f;
    const int tbase = ef * 8;
#pragma unroll
    for (int i = 0; i < 8; i++) {
        int t = tbase + i;
        float ut = su[t], ht = sh[t];
        const float* wi = &g_wihT[t * 192];
        const float* wh = &g_whhT[t * 192];
        a0 += ut * wi[d]; a1 += ut * wi[64 + d]; a2 += ut * wi[128 + d];
        c0 += ht * wh[d]; c1 += ht * wh[64 + d]; c2 += ht * wh[128 + d];
    }
    sp[0][tid] = a0; sp[1][tid] = a1; sp[2][tid] = a2;
    sp[3][tid] = c0; sp[4][tid] = c1; sp[5][tid] = c2;
    __syncthreads();

    if (ef == 0) {
        float A[6];
#pragma unroll
        for (int j = 0; j < 6; j++) {
            float t = 0.f;
#pragma unroll
            for (int e = 0; e < 8; e++) t += sp[j][e * 64 + d];
            A[j] = t;
        }
        float A0 = bih[d] + A[0],       A1 = bih[64 + d] + A[1],  A2 = bih[128 + d] + A[2];
        float C0 = bhh[d] + A[3],       C1 = bhh[64 + d] + A[4],  C2 = bhh[128 + d] + A[5];
        float r = 1.f / (1.f + __expf(-(A0 + C0)));
        float z = 1.f / (1.f + __expf(-(A1 + C1)));
        float n = tanhf(A2 + r * C2);
        shn[d] = (1.f - z) * n + z * sh[d];
    }
    __syncthreads();

    // MLP1: channel j = tid&127, quarter qtr = tid>>7 covers 16 t each
    {
        const int j = tid & 127, qtr = tid >> 7;
        float m = (qtr == 0) ? b1v[j] : 0.f;
#pragma unroll
        for (int i = 0; i < 16; i++) {
            int t = qtr * 16 + i;
            m += shn[t] * w1[t * 128 + j];
        }
        sp[0][tid] = m;
    }
    __syncthreads();
    if (tid < 128)
        smm[tid] = fmaxf(sp[0][tid] + sp[0][128 + tid] + sp[0][256 + tid] + sp[0][384 + tid], 0.f);
    __syncthreads();

    // MLP2: eighth ef handles cc in [ef*16, ef*16+16)
    {
        float op = 0.f;
#pragma unroll
        for (int i = 0; i < 16; i++) {
            int cc = ef * 16 + i;
            op += smm[cc] * w2[cc * 64 + d];
        }
        sp[0][tid] = op;
    }
    __syncthreads();

    if (ef == 0) {
        float t = 0.f;
#pragma unroll
        for (int e = 0; e < 8; e++) t += sp[0][e * 64 + d];
        float oo = shn[d] + b2v[d] + t;
        g_slots[bs * 64 + d] = oo;
        if (out) out[bs * 64 + d] = oo;
        so[d] = oo;
    }
    __syncthreads();

    // LN on new slots (first 2 warps)
    if (ef == 0) {
        float v = so[d];
        float s1 = v, s2 = v * v;
#pragma unroll
        for (int o = 16; o; o >>= 1) {
            s1 += __shfl_xor_sync(0xffffffffu, s1, o);
            s2 += __shfl_xor_sync(0xffffffffu, s2, o);
        }
        if ((d & 31) == 0) { red[d >> 5] = s1; red[2 + (d >> 5)] = s2; }
    }
    __syncthreads();
    if (ef == 0) {
        float S = red[0] + red[1], S2 = red[2] + red[3];
        float mm = S * 0.015625f;
        float var = fmaxf(S2 * 0.015625f - mm * mm, 0.f);
        float inv = rsqrtf(var + 1e-5f);
        shn[d] = (so[d] - mm) * inv * lg[d] + lb[d];
    }
    __syncthreads();

    // q projection: eighth ef handles j in [ef*8, ef*8+8)
    {
        float qp = 0.f;
#pragma unroll
        for (int i = 0; i < 8; i++) {
            int j = ef * 8 + i;
            qp += shn[j] * Wq[j * 64 + d];
        }
        sp[0][tid] = qp;
    }
    __syncthreads();

    if (ef == 0) {
        float t = 0.f;
#pragma unroll
        for (int e = 0; e < 8; e++) t += sp[0][e * 64 + d];
        g_q[bs * 64 + d] = t * 0.125f;
        g_numer[bs * 64 + d] = 0.f;
        if (d == 0) g_denom[bs] = 0.f;
    }
}

// ---------------- launch ----------------
extern "C" void kernel_launch(void* const* d_in, const int* in_sizes, int n_in,
                              void* d_out, int out_size) {
    (void)in_sizes; (void)n_in; (void)out_size;
    const float* x          = (const float*)d_in[0];
    const float* ln_inp_g   = (const float*)d_in[1];
    const float* ln_inp_b   = (const float*)d_in[2];
    const float* ln_slot_g  = (const float*)d_in[3];
    const float* ln_slot_b  = (const float*)d_in[4];
    const float* slots_init = (const float*)d_in[5];
    const float* Wk         = (const float*)d_in[6];
    const float* Wv         = (const float*)d_in[7];
    const float* Wq         = (const float*)d_in[8];
    const float* gwih       = (const float*)d_in[9];
    const float* gwhh       = (const float*)d_in[10];
    const float* gbih       = (const float*)d_in[11];
    const float* gbhh       = (const float*)d_in[12];
    const float* w1         = (const float*)d_in[13];
    const float* b1         = (const float*)d_in[14];
    const float* w2         = (const float*)d_in[15];
    const float* b2         = (const float*)d_in[16];
    float* out = (float*)d_out;

    // 8 launches; 4th (profiled) = update_kernel #1 (the changed kernel).
    init_kernel<<<BB * SS, 64>>>(slots_init, ln_slot_g, ln_slot_b, Wq,
                                 Wk, Wv, gwih, gwhh);                   // 1
    proj_kernel<<<(BB * NN) / 128, 256>>>(x, ln_inp_g, ln_inp_b);       // 2
    for (int it = 0; it < 3; it++) {
        attn_kernel<<<dim3(16, BB), 128>>>();                           // 3,5,7
        update_kernel<<<BB * SS, 512>>>(gbih, gbhh, w1, b1, w2, b2,
                                        ln_slot_g, ln_slot_b, Wq,
                                        it == 2 ? out : nullptr);       // 4,6,8
    }
}